// round 14
// baseline (speedup 1.0000x reference)
#include <cuda_runtime.h>
#include <cuda_bf16.h>
#include <cuda_fp16.h>
#include <cstdint>

#define FIN     128
#define NNODES  100000
#define NEDGE   1600000
#define ETOTMAX (NEDGE + NNODES)

#define BM 256
#define BN 64
#define BK 32
#define BKP 40            // padded SMEM row length (fp16 elems) = 80 bytes
#define A_STG 20480       // 256 rows x 80 B
#define B_STG 5120        // 64 rows x 80 B
#define STG_BYTES (A_STG + B_STG)
#define NSTAGE 4
#define SM_GEMM (NSTAGE * STG_BYTES)

// ---------------- scratch (static device globals; no runtime allocation) ----
__device__ __half g_xh[(size_t)NNODES * 256];   // GEMM output (fp16)
__device__ __half g_a16[(size_t)NNODES * 256];  // GEMM A operand (fp16)
__device__ float g_als[NNODES * 8];
__device__ float g_ald[NNODES * 8];
__device__ int   g_src[ETOTMAX];
__device__ int   g_dst[ETOTMAX];
__device__ int   g_deg[NNODES + 1];
__device__ int   g_rp[NNODES + 1];
__device__ int   g_cur[NNODES];
__device__ int   g_csrc[ETOTMAX];
__device__ int   g_bs[256];
__device__ int   g_is64;
__device__ __half g_wt[3][256 * 256];           // per-layer weight (fp16, [N,K])

// ======================= small PTX helpers ==================================
__device__ __forceinline__ uint32_t smem_to_u32(const void* p) {
    uint32_t a;
    asm("{ .reg .u64 t; cvta.to.shared.u64 t, %1; cvt.u32.u64 %0, t; }"
        : "=r"(a) : "l"(p));
    return a;
}
__device__ __forceinline__ void ldsm4(uint32_t* r, uint32_t addr) {
    asm volatile("ldmatrix.sync.aligned.m8n8.x4.shared.b16 {%0,%1,%2,%3}, [%4];"
                 : "=r"(r[0]), "=r"(r[1]), "=r"(r[2]), "=r"(r[3]) : "r"(addr));
}
__device__ __forceinline__ void mma_fp16(float* c, const uint32_t* a, const uint32_t* b) {
    asm volatile("mma.sync.aligned.m16n8k16.row.col.f32.f16.f16.f32 "
                 "{%0,%1,%2,%3}, {%4,%5,%6,%7}, {%8,%9}, {%0,%1,%2,%3};"
                 : "+f"(c[0]), "+f"(c[1]), "+f"(c[2]), "+f"(c[3])
                 : "r"(a[0]), "r"(a[1]), "r"(a[2]), "r"(a[3]), "r"(b[0]), "r"(b[1]));
}
__device__ __forceinline__ void cp16(uint32_t dst, const void* src, bool valid) {
    int sz = valid ? 16 : 0;
    asm volatile("cp.async.cg.shared.global [%0], [%1], 16, %2;"
                 :: "r"(dst), "l"(src), "r"(sz));
}
#define CP_COMMIT() asm volatile("cp.async.commit_group;" ::: "memory")
#define CP_WAIT(n)  asm volatile("cp.async.wait_group %0;" :: "n"(n) : "memory")

// ------- detect edge dtype (block 0) + zero degree array (all blocks) -------
__global__ void detect_zero_k(const unsigned int* __restrict__ w,
                              int* __restrict__ deg, int n) {
    if (blockIdx.x == 0) {
        __shared__ int flag;
        if (threadIdx.x == 0) flag = 0;
        __syncthreads();
        int local = 0;
        for (int i = threadIdx.x; i < 2048; i += blockDim.x)
            if ((i & 1) && w[i]) local = 1;
        if (local) atomicOr(&flag, 1);
        __syncthreads();
        if (threadIdx.x == 0) g_is64 = flag ? 0 : 1;
    }
    for (int i = blockIdx.x * blockDim.x + threadIdx.x; i < n;
         i += gridDim.x * blockDim.x)
        deg[i] = 0;
}

__global__ void decode_count_k(const void* __restrict__ ei, int ne, int n) {
    int e = blockIdx.x * blockDim.x + threadIdx.x;
    int et = ne + n;
    if (e >= et) return;
    int s, d;
    if (e < ne) {
        if (g_is64) {
            const long long* p = (const long long*)ei;
            s = (int)p[e];
            d = (int)p[(size_t)ne + e];
        } else {
            const int* p = (const int*)ei;
            s = p[e];
            d = p[ne + e];
        }
    } else {
        s = e - ne; d = e - ne;
    }
    g_src[e] = s;
    g_dst[e] = d;
    atomicAdd(&g_deg[d], 1);
}

// ---------------- CSR build --------------------------------------------------
__global__ void scan1_k(const int* __restrict__ deg, int* __restrict__ ex,
                        int* __restrict__ bsums, int n) {
    __shared__ int sh[1024];
    int i = blockIdx.x * 1024 + threadIdx.x;
    int v = (i < n) ? deg[i] : 0;
    sh[threadIdx.x] = v;
    __syncthreads();
    for (int off = 1; off < 1024; off <<= 1) {
        int t = (threadIdx.x >= off) ? sh[threadIdx.x - off] : 0;
        __syncthreads();
        sh[threadIdx.x] += t;
        __syncthreads();
    }
    if (i < n) ex[i] = sh[threadIdx.x] - v;
    if (threadIdx.x == 1023) bsums[blockIdx.x] = sh[1023];
}
__global__ void scan2_k(int* __restrict__ bsums, int nb) {
    __shared__ int sh[256];
    int v = (threadIdx.x < nb) ? bsums[threadIdx.x] : 0;
    sh[threadIdx.x] = v;
    __syncthreads();
    for (int off = 1; off < 256; off <<= 1) {
        int t = (threadIdx.x >= off) ? sh[threadIdx.x - off] : 0;
        __syncthreads();
        sh[threadIdx.x] += t;
        __syncthreads();
    }
    if (threadIdx.x < nb) bsums[threadIdx.x] = sh[threadIdx.x] - v;
}
__global__ void scan3_k(int* __restrict__ rp, const int* __restrict__ bsums,
                        int* __restrict__ cur, int n, int total) {
    int i = blockIdx.x * blockDim.x + threadIdx.x;
    if (i < n) {
        rp[i] += bsums[i >> 10];
        cur[i] = 0;
    }
    if (i == 0) rp[n] = total;
}
__global__ void fill_k(int et) {
    int e = blockIdx.x * blockDim.x + threadIdx.x;
    if (e >= et) return;
    int d = g_dst[e];
    int slot = g_rp[d] + atomicAdd(&g_cur[d], 1);
    g_csrc[slot] = g_src[e];
}

// ---------------- W transpose -> fp16 [N,K] ----------------------------------
__global__ void wt_k(const float* __restrict__ W, __half* __restrict__ o,
                     int K, int NT) {
    int idx = blockIdx.x * blockDim.x + threadIdx.x;
    if (idx >= K * NT) return;
    int n = idx / K, k = idx - n * K;
    o[idx] = __float2half_rn(W[(size_t)k * NT + n]);
}

// ---------------- A convert: fp32 -> fp16 (layer 0 input only) --------------
__global__ void asplit_k(const float* __restrict__ A, __half* __restrict__ o,
                         int total4) {
    int i = blockIdx.x * blockDim.x + threadIdx.x;
    if (i >= total4) return;
    float4 v = reinterpret_cast<const float4*>(A)[i];
    uint2 p;
    __half2 t0 = __floats2half2_rn(v.x, v.y);
    __half2 t1 = __floats2half2_rn(v.z, v.w);
    p.x = *reinterpret_cast<uint32_t*>(&t0);
    p.y = *reinterpret_cast<uint32_t*>(&t1);
    reinterpret_cast<uint2*>(o)[i] = p;
}

// ---------------- HMMA fp16 GEMM (BM=256, warp 32x64, 4-stage cp.async) ------
__device__ __forceinline__ void stage_cp(
    const __half* __restrict__ A, const __half* __restrict__ B,
    uint32_t sbase, int ctaM, int ctaN, int kc, int M, int NT, int Kdim, int t) {
    {
        int r = t;
        int row = ctaM + r;
        bool ok = row < M;
        const __half* p = A + (size_t)row * Kdim + kc;
        uint32_t d = sbase + (uint32_t)(r * BKP) * 2;
#pragma unroll
        for (int j = 0; j < 4; j++)
            cp16(d + j * 16, p + j * 8, ok);
    }
    {
        int n = t >> 2, j = t & 3;
        int gn = ctaN + n;
        bool ok = gn < NT;
        const __half* q = B + (size_t)gn * Kdim + kc + j * 8;
        uint32_t d = sbase + A_STG + (uint32_t)(n * BKP + j * 8) * 2;
        cp16(d, q, ok);
    }
}

__global__ __launch_bounds__(256, 2)
void gemm_mma(const __half* __restrict__ A,
              const __half* __restrict__ B,
              __half* __restrict__ C,
              float* __restrict__ als, float* __restrict__ ald,
              const float* __restrict__ a_src, const float* __restrict__ a_dst,
              int M, int Kdim, int NT, int fuse_al) {
    extern __shared__ char smem[];
    const int t = threadIdx.x;
    const int wid = t >> 5, lane = t & 31;
    const int ctaM = blockIdx.y * BM;
    const int ctaN = blockIdx.x * BN;
    const uint32_t sb = smem_to_u32(smem);

    float acc[2][8][4];
#pragma unroll
    for (int i = 0; i < 2; i++)
#pragma unroll
        for (int j = 0; j < 8; j++)
#pragma unroll
            for (int k = 0; k < 4; k++) acc[i][j][k] = 0.f;

    const int nk = Kdim / BK;

    // 4-stage pipeline prologue: issue stages 0..2
#pragma unroll
    for (int s = 0; s < 3; s++) {
        if (s < nk) {
            stage_cp(A, B, sb + s * STG_BYTES, ctaM, ctaN, s * BK, M, NT, Kdim, t);
            CP_COMMIT();
        }
    }

    for (int i = 0; i < nk; i++) {
        // wait for stage i; up to 2 later groups may remain pending
        if (i + 2 < nk)      { CP_WAIT(2); }
        else if (i + 1 < nk) { CP_WAIT(1); }
        else                 { CP_WAIT(0); }
        __syncthreads();

        // issue stage i+3 into buffer (i+3)%4 (consumed last at iter i-1)
        if (i + 3 < nk) {
            stage_cp(A, B, sb + ((i + 3) % NSTAGE) * STG_BYTES,
                     ctaM, ctaN, (i + 3) * BK, M, NT, Kdim, t);
            CP_COMMIT();
        }

        const uint32_t sBase = sb + (uint32_t)((i % NSTAGE) * STG_BYTES);
#pragma unroll
        for (int kk = 0; kk < 2; kk++) {
            const int kb = kk * 16;
            uint32_t ah[2][4];
#pragma unroll
            for (int mt = 0; mt < 2; mt++) {
                int row_in = wid * 32 + mt * 16 + (lane & 15);
                int koff = kb + ((lane >> 4) << 3);
                uint32_t off = (uint32_t)(row_in * BKP + koff) * 2;
                ldsm4(ah[mt], sBase + off);
            }
            uint32_t bh[8][2];
#pragma unroll
            for (int nt2 = 0; nt2 < 4; nt2++) {
                int n_in = nt2 * 16 + ((lane >> 4) << 3) + (lane & 7);
                int koff = kb + ((lane >> 3) & 1) * 8;
                uint32_t off = (uint32_t)(n_in * BKP + koff) * 2;
                uint32_t r[4];
                ldsm4(r, sBase + A_STG + off);
                bh[nt2 * 2][0] = r[0]; bh[nt2 * 2][1] = r[1];
                bh[nt2 * 2 + 1][0] = r[2]; bh[nt2 * 2 + 1][1] = r[3];
            }
#pragma unroll
            for (int mt = 0; mt < 2; mt++)
#pragma unroll
                for (int nt = 0; nt < 8; nt++)
                    mma_fp16(acc[mt][nt], ah[mt], bh[nt]);
        }
    }

    // ---- epilogue: write C (fp16) + fused attention logits ----
    // fuse_al==1: 2 heads of C=32 per warp.  fuse_al==2: single head over NT cols.
    const int grp = lane >> 2, q = lane & 3;
#pragma unroll
    for (int mt = 0; mt < 2; mt++) {
#pragma unroll
        for (int half = 0; half < 2; half++) {
            int row = ctaM + wid * 32 + mt * 16 + grp + half * 8;
            float as_tot = 0.f, ad_tot = 0.f;
#pragma unroll
            for (int hg = 0; hg < 2; hg++) {
                float as_p = 0.f, ad_p = 0.f;
#pragma unroll
                for (int nt4 = 0; nt4 < 4; nt4++) {
                    int nt = hg * 4 + nt4;
                    int gcol = ctaN + nt * 8 + q * 2;
                    float v0 = acc[mt][nt][half * 2 + 0];
                    float v1 = acc[mt][nt][half * 2 + 1];
                    bool okc = gcol < NT;
                    if (row < M && okc)
                        *(__half2*)&C[(size_t)row * NT + gcol] = __floats2half2_rn(v0, v1);
                    if (fuse_al && okc) {
                        as_p += v0 * a_src[gcol] + v1 * a_src[gcol + 1];
                        ad_p += v0 * a_dst[gcol] + v1 * a_dst[gcol + 1];
                    }
                }
                if (fuse_al == 1) {
                    as_p += __shfl_xor_sync(0xffffffffu, as_p, 1);
                    as_p += __shfl_xor_sync(0xffffffffu, as_p, 2);
                    ad_p += __shfl_xor_sync(0xffffffffu, ad_p, 1);
                    ad_p += __shfl_xor_sync(0xffffffffu, ad_p, 2);
                    int head = (ctaN + hg * 32) >> 5;
                    if (q == 0 && row < M) {
                        als[(size_t)row * 8 + head] = as_p;
                        ald[(size_t)row * 8 + head] = ad_p;
                    }
                } else {
                    as_tot += as_p;
                    ad_tot += ad_p;
                }
            }
            if (fuse_al == 2) {
                as_tot += __shfl_xor_sync(0xffffffffu, as_tot, 1);
                as_tot += __shfl_xor_sync(0xffffffffu, as_tot, 2);
                ad_tot += __shfl_xor_sync(0xffffffffu, ad_tot, 1);
                ad_tot += __shfl_xor_sync(0xffffffffu, ad_tot, 2);
                if (q == 0 && row < M) {
                    als[row] = as_tot;
                    ald[row] = ad_tot;
                }
            }
        }
    }
}

// ------- fused SINGLE-PASS softmax + aggregate + bias(+elu): warp per dst ---
// 4-edge unrolled main loop for memory-level parallelism.
template <int H, int C, int OUTMODE>
__global__ void gat_agg_h(const __half* __restrict__ x,
                          const float* __restrict__ als,
                          const float* __restrict__ ald,
                          const int* __restrict__ rp,
                          const int* __restrict__ cs,
                          float* __restrict__ out,
                          __half* __restrict__ oh,
                          const float* __restrict__ bias,
                          int Nn, int do_elu) {
    constexpr int HC = H * C;
    int n = (blockIdx.x * blockDim.x + threadIdx.x) >> 5;
    int lane = threadIdx.x & 31;
    if (n >= Nn) return;

    int start = rp[n], end = rp[n + 1];
    float aldv = (lane < H) ? ald[n * H + lane] : 0.f;

    const int col0 = lane * 8;
    const bool act = col0 < HC;
    const int alane = act ? (col0 / C) : 0;
    float acc[8];
#pragma unroll
    for (int i = 0; i < 8; i++) acc[i] = 0.f;
    float sacc = 0.f;

    int k = start;
    for (; k + 3 < end; k += 4) {
        int s0 = cs[k], s1 = cs[k + 1], s2 = cs[k + 2], s3 = cs[k + 3];
        float e0 = 0.f, e1 = 0.f, e2 = 0.f, e3 = 0.f;
        if (lane < H) {
            float v0 = als[s0 * H + lane] + aldv;
            float v1 = als[s1 * H + lane] + aldv;
            float v2 = als[s2 * H + lane] + aldv;
            float v3 = als[s3 * H + lane] + aldv;
            v0 = v0 > 0.f ? v0 : 0.2f * v0;
            v1 = v1 > 0.f ? v1 : 0.2f * v1;
            v2 = v2 > 0.f ? v2 : 0.2f * v2;
            v3 = v3 > 0.f ? v3 : 0.2f * v3;
            e0 = __expf(v0); e1 = __expf(v1);
            e2 = __expf(v2); e3 = __expf(v3);
            sacc += (e0 + e1) + (e2 + e3);
        }
        float a0 = __shfl_sync(0xffffffffu, e0, alane);
        float a1 = __shfl_sync(0xffffffffu, e1, alane);
        float a2 = __shfl_sync(0xffffffffu, e2, alane);
        float a3 = __shfl_sync(0xffffffffu, e3, alane);
        if (act) {
            uint4 w0 = *(const uint4*)(x + (size_t)s0 * HC + col0);
            uint4 w1 = *(const uint4*)(x + (size_t)s1 * HC + col0);
            uint4 w2 = *(const uint4*)(x + (size_t)s2 * HC + col0);
            uint4 w3 = *(const uint4*)(x + (size_t)s3 * HC + col0);
            float2 f;
            f = __half22float2(*(__half2*)&w0.x); acc[0] += f.x * a0; acc[1] += f.y * a0;
            f = __half22float2(*(__half2*)&w0.y); acc[2] += f.x * a0; acc[3] += f.y * a0;
            f = __half22float2(*(__half2*)&w0.z); acc[4] += f.x * a0; acc[5] += f.y * a0;
            f = __half22float2(*(__half2*)&w0.w); acc[6] += f.x * a0; acc[7] += f.y * a0;
            f = __half22float2(*(__half2*)&w1.x); acc[0] += f.x * a1; acc[1] += f.y * a1;
            f = __half22float2(*(__half2*)&w1.y); acc[2] += f.x * a1; acc[3] += f.y * a1;
            f = __half22float2(*(__half2*)&w1.z); acc[4] += f.x * a1; acc[5] += f.y * a1;
            f = __half22float2(*(__half2*)&w1.w); acc[6] += f.x * a1; acc[7] += f.y * a1;
            f = __half22float2(*(__half2*)&w2.x); acc[0] += f.x * a2; acc[1] += f.y * a2;
            f = __half22float2(*(__half2*)&w2.y); acc[2] += f.x * a2; acc[3] += f.y * a2;
            f = __half22float2(*(__half2*)&w2.z); acc[4] += f.x * a2; acc[5] += f.y * a2;
            f = __half22float2(*(__half2*)&w2.w); acc[6] += f.x * a2; acc[7] += f.y * a2;
            f = __half22float2(*(__half2*)&w3.x); acc[0] += f.x * a3; acc[1] += f.y * a3;
            f = __half22float2(*(__half2*)&w3.y); acc[2] += f.x * a3; acc[3] += f.y * a3;
            f = __half22float2(*(__half2*)&w3.z); acc[4] += f.x * a3; acc[5] += f.y * a3;
            f = __half22float2(*(__half2*)&w3.w); acc[6] += f.x * a3; acc[7] += f.y * a3;
        }
    }
    for (; k < end; k++) {
        int s0 = cs[k];
        float e0 = 0.f;
        if (lane < H) {
            float v0 = als[s0 * H + lane] + aldv;
            v0 = v0 > 0.f ? v0 : 0.2f * v0;
            e0 = __expf(v0);
            sacc += e0;
        }
        float a0 = __shfl_sync(0xffffffffu, e0, alane);
        if (act) {
            uint4 w0 = *(const uint4*)(x + (size_t)s0 * HC + col0);
            float2 f;
            f = __half22float2(*(__half2*)&w0.x); acc[0] += f.x * a0; acc[1] += f.y * a0;
            f = __half22float2(*(__half2*)&w0.y); acc[2] += f.x * a0; acc[3] += f.y * a0;
            f = __half22float2(*(__half2*)&w0.z); acc[4] += f.x * a0; acc[5] += f.y * a0;
            f = __half22float2(*(__half2*)&w0.w); acc[6] += f.x * a0; acc[7] += f.y * a0;
        }
    }

    float inv_s = (lane < H && sacc > 0.f) ? __frcp_rn(sacc) : 0.f;
    float scale = __shfl_sync(0xffffffffu, inv_s, alane);

    if (act) {
        float o[8];
#pragma unroll
        for (int i = 0; i < 8; i++) {
            float v = acc[i] * scale + bias[col0 + i];
            if (do_elu) v = v > 0.f ? v : expm1f(v);
            o[i] = v;
        }
        if (OUTMODE == 0) {
            float* od = out + (size_t)n * HC + col0;
            *(float4*)(od)     = make_float4(o[0], o[1], o[2], o[3]);
            *(float4*)(od + 4) = make_float4(o[4], o[5], o[6], o[7]);
        } else {
            uint4 p;
            __half2 t0 = __floats2half2_rn(o[0], o[1]);
            __half2 t1 = __floats2half2_rn(o[2], o[3]);
            __half2 t2 = __floats2half2_rn(o[4], o[5]);
            __half2 t3 = __floats2half2_rn(o[6], o[7]);
            p.x = *(uint32_t*)&t0; p.y = *(uint32_t*)&t1;
            p.z = *(uint32_t*)&t2; p.w = *(uint32_t*)&t3;
            *(uint4*)(oh + (size_t)n * HC + col0) = p;
        }
    }
}

// ---------------- launcher (single stream — graph-capture friendly) ---------
extern "C" void kernel_launch(void* const* d_in, const int* in_sizes, int n_in,
                              void* d_out, int out_size) {
    const float* feats = (const float*)d_in[0];
    const void*  ei    = d_in[1];
    const float* W0  = (const float*)d_in[2];
    const float* as0 = (const float*)d_in[3];
    const float* ad0 = (const float*)d_in[4];
    const float* b0  = (const float*)d_in[5];
    const float* W1  = (const float*)d_in[6];
    const float* as1 = (const float*)d_in[7];
    const float* ad1 = (const float*)d_in[8];
    const float* b1  = (const float*)d_in[9];
    const float* W2  = (const float*)d_in[10];
    const float* as2 = (const float*)d_in[11];
    const float* ad2 = (const float*)d_in[12];
    const float* b2  = (const float*)d_in[13];

    int N  = in_sizes[0] / FIN;
    int NE = in_sizes[1] / 2;
    int ET = NE + N;
    float* out = (float*)d_out;
    (void)n_in; (void)out_size;

    __half *pxh, *pa16, *pwt;
    float *pals, *pald;
    int *pdeg, *prp, *pcur, *pcs, *pbs;
    cudaGetSymbolAddress((void**)&pxh,  g_xh);
    cudaGetSymbolAddress((void**)&pa16, g_a16);
    cudaGetSymbolAddress((void**)&pals, g_als);
    cudaGetSymbolAddress((void**)&pald, g_ald);
    cudaGetSymbolAddress((void**)&pdeg, g_deg);
    cudaGetSymbolAddress((void**)&prp,  g_rp);
    cudaGetSymbolAddress((void**)&pcur, g_cur);
    cudaGetSymbolAddress((void**)&pcs,  g_csrc);
    cudaGetSymbolAddress((void**)&pbs,  g_bs);
    cudaGetSymbolAddress((void**)&pwt,  g_wt);

    cudaFuncSetAttribute(gemm_mma, cudaFuncAttributeMaxDynamicSharedMemorySize, SM_GEMM);

    int ethreads = (ET + 255) / 256;
    int nwarps_b = (N * 32 + 255) / 256;
    dim3 grid256(4, (N + BM - 1) / BM);
    dim3 grid40(1, (N + BM - 1) / BM);

    // (1) dtype detect + zero(deg)
    detect_zero_k<<<256, 256>>>((const unsigned int*)ei, pdeg, N + 1);
    // (2) layer-0 weights
    wt_k<<<(256 * 128 + 255) / 256, 256>>>(W0, pwt + 0 * 65536, 128, 256);
    // (3) layer-0 A convert
    asplit_k<<<(N * 128 / 4 + 255) / 256, 256>>>(feats, pa16, N * 128 / 4);
    // (4) layer-0 GEMM  <-- profiled launch
    gemm_mma<<<grid256, 256, SM_GEMM>>>(pa16, pwt, pxh, pals, pald,
                                        as0, ad0, N, 128, 256, 1);

    // --- CSR build (must complete before agg0) ---
    decode_count_k<<<ethreads, 256>>>(ei, NE, N);
    int nb1 = (N + 1023) / 1024;
    scan1_k<<<nb1, 1024>>>(pdeg, prp, pbs, N);
    scan2_k<<<1, 256>>>(pbs, nb1);
    scan3_k<<<(N + 255) / 256, 256>>>(prp, pbs, pcur, N, ET);
    fill_k<<<ethreads, 256>>>(ET);

    // --- layer 0 aggregation (writes fp16 A for layer 1) ---
    gat_agg_h<8, 32, 1><<<nwarps_b, 256>>>(pxh, pals, pald, prp, pcs,
                                           nullptr, pa16, b0, N, 1);

    // --- layer 1: 256 -> 8x32 ---
    wt_k<<<(256 * 256 + 255) / 256, 256>>>(W1, pwt + 1 * 65536, 256, 256);
    gemm_mma<<<grid256, 256, SM_GEMM>>>(pa16, pwt + 65536, pxh,
                                        pals, pald, as1, ad1, N, 256, 256, 1);
    gat_agg_h<8, 32, 1><<<nwarps_b, 256>>>(pxh, pals, pald, prp, pcs,
                                           nullptr, pa16, b1, N, 1);

    // --- layer 2: 256 -> 1x40 (al fused into GEMM epilogue, mode 2) ---
    wt_k<<<(40 * 256 + 255) / 256, 256>>>(W2, pwt + 2 * 65536, 256, 40);
    gemm_mma<<<grid40, 256, SM_GEMM>>>(pa16, pwt + 2 * 65536,
                                       pxh, pals, pald, as2, ad2, N, 256, 40, 2);
    gat_agg_h<1, 40, 0><<<nwarps_b, 256>>>(pxh, pals, pald, prp, pcs,
                                           out, nullptr, b2, N, 0);
}

// round 15
// speedup vs baseline: 1.0471x; 1.0471x over previous
#include <cuda_runtime.h>
#include <cuda_bf16.h>
#include <cuda_fp16.h>
#include <cstdint>

#define FIN     128
#define NNODES  100000
#define NEDGE   1600000
#define ETOTMAX (NEDGE + NNODES)

#define BM 256
#define BN 64
#define BK 32
#define BKP 40            // padded SMEM row length (fp16 elems) = 80 bytes
#define A_STG 20480       // 256 rows x 80 B
#define B_STG 5120        // 64 rows x 80 B
#define STG_BYTES (A_STG + B_STG)
#define NSTAGE 2
#define SM_GEMM (NSTAGE * STG_BYTES)

// ---------------- scratch (static device globals; no runtime allocation) ----
__device__ __half g_xh[(size_t)NNODES * 256];   // GEMM output (fp16)
__device__ __half g_a16[(size_t)NNODES * 256];  // GEMM A operand (fp16)
__device__ float g_als[NNODES * 8];
__device__ float g_ald[NNODES * 8];
__device__ int   g_src[ETOTMAX];
__device__ int   g_dst[ETOTMAX];
__device__ int   g_deg[NNODES + 1];
__device__ int   g_rp[NNODES + 1];
__device__ int   g_cur[NNODES];
__device__ int   g_csrc[ETOTMAX];
__device__ int   g_bs[256];
__device__ int   g_is64;
__device__ __half g_wt[3][256 * 256];           // per-layer weight (fp16, [N,K])

// ======================= small PTX helpers ==================================
__device__ __forceinline__ uint32_t smem_to_u32(const void* p) {
    uint32_t a;
    asm("{ .reg .u64 t; cvta.to.shared.u64 t, %1; cvt.u32.u64 %0, t; }"
        : "=r"(a) : "l"(p));
    return a;
}
__device__ __forceinline__ void ldsm4(uint32_t* r, uint32_t addr) {
    asm volatile("ldmatrix.sync.aligned.m8n8.x4.shared.b16 {%0,%1,%2,%3}, [%4];"
                 : "=r"(r[0]), "=r"(r[1]), "=r"(r[2]), "=r"(r[3]) : "r"(addr));
}
__device__ __forceinline__ void mma_fp16(float* c, const uint32_t* a, const uint32_t* b) {
    asm volatile("mma.sync.aligned.m16n8k16.row.col.f32.f16.f16.f32 "
                 "{%0,%1,%2,%3}, {%4,%5,%6,%7}, {%8,%9}, {%0,%1,%2,%3};"
                 : "+f"(c[0]), "+f"(c[1]), "+f"(c[2]), "+f"(c[3])
                 : "r"(a[0]), "r"(a[1]), "r"(a[2]), "r"(a[3]), "r"(b[0]), "r"(b[1]));
}
__device__ __forceinline__ void cp16(uint32_t dst, const void* src, bool valid) {
    int sz = valid ? 16 : 0;
    asm volatile("cp.async.cg.shared.global [%0], [%1], 16, %2;"
                 :: "r"(dst), "l"(src), "r"(sz));
}
#define CP_COMMIT() asm volatile("cp.async.commit_group;" ::: "memory")
#define CP_WAIT(n)  asm volatile("cp.async.wait_group %0;" :: "n"(n) : "memory")

// ------- detect edge dtype (block 0) + zero degree array (all blocks) -------
__global__ void detect_zero_k(const unsigned int* __restrict__ w,
                              int* __restrict__ deg, int n) {
    if (blockIdx.x == 0) {
        __shared__ int flag;
        if (threadIdx.x == 0) flag = 0;
        __syncthreads();
        int local = 0;
        for (int i = threadIdx.x; i < 2048; i += blockDim.x)
            if ((i & 1) && w[i]) local = 1;
        if (local) atomicOr(&flag, 1);
        __syncthreads();
        if (threadIdx.x == 0) g_is64 = flag ? 0 : 1;
    }
    for (int i = blockIdx.x * blockDim.x + threadIdx.x; i < n;
         i += gridDim.x * blockDim.x)
        deg[i] = 0;
}

__global__ void decode_count_k(const void* __restrict__ ei, int ne, int n) {
    int e = blockIdx.x * blockDim.x + threadIdx.x;
    int et = ne + n;
    if (e >= et) return;
    int s, d;
    if (e < ne) {
        if (g_is64) {
            const long long* p = (const long long*)ei;
            s = (int)p[e];
            d = (int)p[(size_t)ne + e];
        } else {
            const int* p = (const int*)ei;
            s = p[e];
            d = p[ne + e];
        }
    } else {
        s = e - ne; d = e - ne;
    }
    g_src[e] = s;
    g_dst[e] = d;
    atomicAdd(&g_deg[d], 1);
}

// ---------------- CSR build --------------------------------------------------
__global__ void scan1_k(const int* __restrict__ deg, int* __restrict__ ex,
                        int* __restrict__ bsums, int n) {
    __shared__ int sh[1024];
    int i = blockIdx.x * 1024 + threadIdx.x;
    int v = (i < n) ? deg[i] : 0;
    sh[threadIdx.x] = v;
    __syncthreads();
    for (int off = 1; off < 1024; off <<= 1) {
        int t = (threadIdx.x >= off) ? sh[threadIdx.x - off] : 0;
        __syncthreads();
        sh[threadIdx.x] += t;
        __syncthreads();
    }
    if (i < n) ex[i] = sh[threadIdx.x] - v;
    if (threadIdx.x == 1023) bsums[blockIdx.x] = sh[1023];
}
__global__ void scan2_k(int* __restrict__ bsums, int nb) {
    __shared__ int sh[256];
    int v = (threadIdx.x < nb) ? bsums[threadIdx.x] : 0;
    sh[threadIdx.x] = v;
    __syncthreads();
    for (int off = 1; off < 256; off <<= 1) {
        int t = (threadIdx.x >= off) ? sh[threadIdx.x - off] : 0;
        __syncthreads();
        sh[threadIdx.x] += t;
        __syncthreads();
    }
    if (threadIdx.x < nb) bsums[threadIdx.x] = sh[threadIdx.x] - v;
}
__global__ void scan3_k(int* __restrict__ rp, const int* __restrict__ bsums,
                        int* __restrict__ cur, int n, int total) {
    int i = blockIdx.x * blockDim.x + threadIdx.x;
    if (i < n) {
        rp[i] += bsums[i >> 10];
        cur[i] = 0;
    }
    if (i == 0) rp[n] = total;
}
__global__ void fill_k(int et) {
    int e = blockIdx.x * blockDim.x + threadIdx.x;
    if (e >= et) return;
    int d = g_dst[e];
    int slot = g_rp[d] + atomicAdd(&g_cur[d], 1);
    g_csrc[slot] = g_src[e];
}

// ---------------- W transpose -> fp16 [N,K] ----------------------------------
__global__ void wt_k(const float* __restrict__ W, __half* __restrict__ o,
                     int K, int NT) {
    int idx = blockIdx.x * blockDim.x + threadIdx.x;
    if (idx >= K * NT) return;
    int n = idx / K, k = idx - n * K;
    o[idx] = __float2half_rn(W[(size_t)k * NT + n]);
}

// ---------------- A convert: fp32 -> fp16 (layer 0 input only) --------------
__global__ void asplit_k(const float* __restrict__ A, __half* __restrict__ o,
                         int total4) {
    int i = blockIdx.x * blockDim.x + threadIdx.x;
    if (i >= total4) return;
    float4 v = reinterpret_cast<const float4*>(A)[i];
    uint2 p;
    __half2 t0 = __floats2half2_rn(v.x, v.y);
    __half2 t1 = __floats2half2_rn(v.z, v.w);
    p.x = *reinterpret_cast<uint32_t*>(&t0);
    p.y = *reinterpret_cast<uint32_t*>(&t1);
    reinterpret_cast<uint2*>(o)[i] = p;
}

// ---------------- HMMA fp16 GEMM (BM=256, warp 32x64, 2-stage cp.async) ------
__device__ __forceinline__ void stage_cp(
    const __half* __restrict__ A, const __half* __restrict__ B,
    uint32_t sbase, int ctaM, int ctaN, int kc, int M, int NT, int Kdim, int t) {
    {
        int r = t;
        int row = ctaM + r;
        bool ok = row < M;
        const __half* p = A + (size_t)row * Kdim + kc;
        uint32_t d = sbase + (uint32_t)(r * BKP) * 2;
#pragma unroll
        for (int j = 0; j < 4; j++)
            cp16(d + j * 16, p + j * 8, ok);
    }
    {
        int n = t >> 2, j = t & 3;
        int gn = ctaN + n;
        bool ok = gn < NT;
        const __half* q = B + (size_t)gn * Kdim + kc + j * 8;
        uint32_t d = sbase + A_STG + (uint32_t)(n * BKP + j * 8) * 2;
        cp16(d, q, ok);
    }
}

__global__ __launch_bounds__(256, 2)
void gemm_mma(const __half* __restrict__ A,
              const __half* __restrict__ B,
              __half* __restrict__ C,
              float* __restrict__ als, float* __restrict__ ald,
              const float* __restrict__ a_src, const float* __restrict__ a_dst,
              int M, int Kdim, int NT, int fuse_al) {
    extern __shared__ char smem[];
    const int t = threadIdx.x;
    const int wid = t >> 5, lane = t & 31;
    const int ctaM = blockIdx.y * BM;
    const int ctaN = blockIdx.x * BN;
    const uint32_t sb = smem_to_u32(smem);

    float acc[2][8][4];
#pragma unroll
    for (int i = 0; i < 2; i++)
#pragma unroll
        for (int j = 0; j < 8; j++)
#pragma unroll
            for (int k = 0; k < 4; k++) acc[i][j][k] = 0.f;

    const int nk = Kdim / BK;

    stage_cp(A, B, sb, ctaM, ctaN, 0, M, NT, Kdim, t);
    CP_COMMIT();

    for (int i = 0; i < nk; i++) {
        if (i + 1 < nk) {
            stage_cp(A, B, sb + ((i + 1) & 1) * STG_BYTES,
                     ctaM, ctaN, (i + 1) * BK, M, NT, Kdim, t);
            CP_COMMIT();
            CP_WAIT(1);
        } else {
            CP_WAIT(0);
        }
        __syncthreads();

        const uint32_t sBase = sb + (uint32_t)((i & 1) * STG_BYTES);
#pragma unroll
        for (int kk = 0; kk < 2; kk++) {
            const int kb = kk * 16;
            uint32_t ah[2][4];
#pragma unroll
            for (int mt = 0; mt < 2; mt++) {
                int row_in = wid * 32 + mt * 16 + (lane & 15);
                int koff = kb + ((lane >> 4) << 3);
                uint32_t off = (uint32_t)(row_in * BKP + koff) * 2;
                ldsm4(ah[mt], sBase + off);
            }
            uint32_t bh[8][2];
#pragma unroll
            for (int nt2 = 0; nt2 < 4; nt2++) {
                int n_in = nt2 * 16 + ((lane >> 4) << 3) + (lane & 7);
                int koff = kb + ((lane >> 3) & 1) * 8;
                uint32_t off = (uint32_t)(n_in * BKP + koff) * 2;
                uint32_t r[4];
                ldsm4(r, sBase + A_STG + off);
                bh[nt2 * 2][0] = r[0]; bh[nt2 * 2][1] = r[1];
                bh[nt2 * 2 + 1][0] = r[2]; bh[nt2 * 2 + 1][1] = r[3];
            }
#pragma unroll
            for (int mt = 0; mt < 2; mt++)
#pragma unroll
                for (int nt = 0; nt < 8; nt++)
                    mma_fp16(acc[mt][nt], ah[mt], bh[nt]);
        }
        __syncthreads();
    }

    // ---- epilogue: write C (fp16) + fused attention logits ----
    // fuse_al==1: 2 heads of C=32 per warp.  fuse_al==2: single head over NT cols.
    const int grp = lane >> 2, q = lane & 3;
#pragma unroll
    for (int mt = 0; mt < 2; mt++) {
#pragma unroll
        for (int half = 0; half < 2; half++) {
            int row = ctaM + wid * 32 + mt * 16 + grp + half * 8;
            float as_tot = 0.f, ad_tot = 0.f;
#pragma unroll
            for (int hg = 0; hg < 2; hg++) {
                float as_p = 0.f, ad_p = 0.f;
#pragma unroll
                for (int nt4 = 0; nt4 < 4; nt4++) {
                    int nt = hg * 4 + nt4;
                    int gcol = ctaN + nt * 8 + q * 2;
                    float v0 = acc[mt][nt][half * 2 + 0];
                    float v1 = acc[mt][nt][half * 2 + 1];
                    bool okc = gcol < NT;
                    if (row < M && okc)
                        *(__half2*)&C[(size_t)row * NT + gcol] = __floats2half2_rn(v0, v1);
                    if (fuse_al && okc) {
                        as_p += v0 * a_src[gcol] + v1 * a_src[gcol + 1];
                        ad_p += v0 * a_dst[gcol] + v1 * a_dst[gcol + 1];
                    }
                }
                if (fuse_al == 1) {
                    as_p += __shfl_xor_sync(0xffffffffu, as_p, 1);
                    as_p += __shfl_xor_sync(0xffffffffu, as_p, 2);
                    ad_p += __shfl_xor_sync(0xffffffffu, ad_p, 1);
                    ad_p += __shfl_xor_sync(0xffffffffu, ad_p, 2);
                    int head = (ctaN + hg * 32) >> 5;
                    if (q == 0 && row < M) {
                        als[(size_t)row * 8 + head] = as_p;
                        ald[(size_t)row * 8 + head] = ad_p;
                    }
                } else {
                    as_tot += as_p;
                    ad_tot += ad_p;
                }
            }
            if (fuse_al == 2) {
                as_tot += __shfl_xor_sync(0xffffffffu, as_tot, 1);
                as_tot += __shfl_xor_sync(0xffffffffu, as_tot, 2);
                ad_tot += __shfl_xor_sync(0xffffffffu, ad_tot, 1);
                ad_tot += __shfl_xor_sync(0xffffffffu, ad_tot, 2);
                if (q == 0 && row < M) {
                    als[row] = as_tot;
                    ald[row] = ad_tot;
                }
            }
        }
    }
}

// ------- fused SINGLE-PASS softmax + aggregate + bias(+elu): warp per dst ---
// 2-edge unrolled main loop for memory-level parallelism.
template <int H, int C, int OUTMODE>
__global__ void gat_agg_h(const __half* __restrict__ x,
                          const float* __restrict__ als,
                          const float* __restrict__ ald,
                          const int* __restrict__ rp,
                          const int* __restrict__ cs,
                          float* __restrict__ out,
                          __half* __restrict__ oh,
                          const float* __restrict__ bias,
                          int Nn, int do_elu) {
    constexpr int HC = H * C;
    int n = (blockIdx.x * blockDim.x + threadIdx.x) >> 5;
    int lane = threadIdx.x & 31;
    if (n >= Nn) return;

    int start = rp[n], end = rp[n + 1];
    float aldv = (lane < H) ? ald[n * H + lane] : 0.f;

    const int col0 = lane * 8;
    const bool act = col0 < HC;
    const int alane = act ? (col0 / C) : 0;
    float acc[8];
#pragma unroll
    for (int i = 0; i < 8; i++) acc[i] = 0.f;
    float sacc = 0.f;

    int k = start;
    for (; k + 1 < end; k += 2) {
        int s0 = cs[k], s1 = cs[k + 1];
        float e0 = 0.f, e1 = 0.f;
        if (lane < H) {
            float v0 = als[s0 * H + lane] + aldv;
            float v1 = als[s1 * H + lane] + aldv;
            v0 = v0 > 0.f ? v0 : 0.2f * v0;
            v1 = v1 > 0.f ? v1 : 0.2f * v1;
            e0 = __expf(v0);
            e1 = __expf(v1);
            sacc += e0 + e1;
        }
        float a0 = __shfl_sync(0xffffffffu, e0, alane);
        float a1 = __shfl_sync(0xffffffffu, e1, alane);
        if (act) {
            uint4 w0 = *(const uint4*)(x + (size_t)s0 * HC + col0);
            uint4 w1 = *(const uint4*)(x + (size_t)s1 * HC + col0);
            float2 f;
            f = __half22float2(*(__half2*)&w0.x); acc[0] += f.x * a0; acc[1] += f.y * a0;
            f = __half22float2(*(__half2*)&w0.y); acc[2] += f.x * a0; acc[3] += f.y * a0;
            f = __half22float2(*(__half2*)&w0.z); acc[4] += f.x * a0; acc[5] += f.y * a0;
            f = __half22float2(*(__half2*)&w0.w); acc[6] += f.x * a0; acc[7] += f.y * a0;
            f = __half22float2(*(__half2*)&w1.x); acc[0] += f.x * a1; acc[1] += f.y * a1;
            f = __half22float2(*(__half2*)&w1.y); acc[2] += f.x * a1; acc[3] += f.y * a1;
            f = __half22float2(*(__half2*)&w1.z); acc[4] += f.x * a1; acc[5] += f.y * a1;
            f = __half22float2(*(__half2*)&w1.w); acc[6] += f.x * a1; acc[7] += f.y * a1;
        }
    }
    if (k < end) {
        int s0 = cs[k];
        float e0 = 0.f;
        if (lane < H) {
            float v0 = als[s0 * H + lane] + aldv;
            v0 = v0 > 0.f ? v0 : 0.2f * v0;
            e0 = __expf(v0);
            sacc += e0;
        }
        float a0 = __shfl_sync(0xffffffffu, e0, alane);
        if (act) {
            uint4 w0 = *(const uint4*)(x + (size_t)s0 * HC + col0);
            float2 f;
            f = __half22float2(*(__half2*)&w0.x); acc[0] += f.x * a0; acc[1] += f.y * a0;
            f = __half22float2(*(__half2*)&w0.y); acc[2] += f.x * a0; acc[3] += f.y * a0;
            f = __half22float2(*(__half2*)&w0.z); acc[4] += f.x * a0; acc[5] += f.y * a0;
            f = __half22float2(*(__half2*)&w0.w); acc[6] += f.x * a0; acc[7] += f.y * a0;
        }
    }

    float inv_s = (lane < H && sacc > 0.f) ? __frcp_rn(sacc) : 0.f;
    float scale = __shfl_sync(0xffffffffu, inv_s, alane);

    if (act) {
        float o[8];
#pragma unroll
        for (int i = 0; i < 8; i++) {
            float v = acc[i] * scale + bias[col0 + i];
            if (do_elu) v = v > 0.f ? v : expm1f(v);
            o[i] = v;
        }
        if (OUTMODE == 0) {
            float* od = out + (size_t)n * HC + col0;
            *(float4*)(od)     = make_float4(o[0], o[1], o[2], o[3]);
            *(float4*)(od + 4) = make_float4(o[4], o[5], o[6], o[7]);
        } else {
            uint4 p;
            __half2 t0 = __floats2half2_rn(o[0], o[1]);
            __half2 t1 = __floats2half2_rn(o[2], o[3]);
            __half2 t2 = __floats2half2_rn(o[4], o[5]);
            __half2 t3 = __floats2half2_rn(o[6], o[7]);
            p.x = *(uint32_t*)&t0; p.y = *(uint32_t*)&t1;
            p.z = *(uint32_t*)&t2; p.w = *(uint32_t*)&t3;
            *(uint4*)(oh + (size_t)n * HC + col0) = p;
        }
    }
}

// ---------------- launcher (single stream — graph-capture friendly) ---------
extern "C" void kernel_launch(void* const* d_in, const int* in_sizes, int n_in,
                              void* d_out, int out_size) {
    const float* feats = (const float*)d_in[0];
    const void*  ei    = d_in[1];
    const float* W0  = (const float*)d_in[2];
    const float* as0 = (const float*)d_in[3];
    const float* ad0 = (const float*)d_in[4];
    const float* b0  = (const float*)d_in[5];
    const float* W1  = (const float*)d_in[6];
    const float* as1 = (const float*)d_in[7];
    const float* ad1 = (const float*)d_in[8];
    const float* b1  = (const float*)d_in[9];
    const float* W2  = (const float*)d_in[10];
    const float* as2 = (const float*)d_in[11];
    const float* ad2 = (const float*)d_in[12];
    const float* b2  = (const float*)d_in[13];

    int N  = in_sizes[0] / FIN;
    int NE = in_sizes[1] / 2;
    int ET = NE + N;
    float* out = (float*)d_out;
    (void)n_in; (void)out_size;

    __half *pxh, *pa16, *pwt;
    float *pals, *pald;
    int *pdeg, *prp, *pcur, *pcs, *pbs;
    cudaGetSymbolAddress((void**)&pxh,  g_xh);
    cudaGetSymbolAddress((void**)&pa16, g_a16);
    cudaGetSymbolAddress((void**)&pals, g_als);
    cudaGetSymbolAddress((void**)&pald, g_ald);
    cudaGetSymbolAddress((void**)&pdeg, g_deg);
    cudaGetSymbolAddress((void**)&prp,  g_rp);
    cudaGetSymbolAddress((void**)&pcur, g_cur);
    cudaGetSymbolAddress((void**)&pcs,  g_csrc);
    cudaGetSymbolAddress((void**)&pbs,  g_bs);
    cudaGetSymbolAddress((void**)&pwt,  g_wt);

    cudaFuncSetAttribute(gemm_mma, cudaFuncAttributeMaxDynamicSharedMemorySize, SM_GEMM);

    int ethreads = (ET + 255) / 256;
    int nwarps_b = (N * 32 + 255) / 256;
    dim3 grid256(4, (N + BM - 1) / BM);
    dim3 grid40(1, (N + BM - 1) / BM);

    // (1) dtype detect + zero(deg)
    detect_zero_k<<<256, 256>>>((const unsigned int*)ei, pdeg, N + 1);
    // (2) layer-0 weights
    wt_k<<<(256 * 128 + 255) / 256, 256>>>(W0, pwt + 0 * 65536, 128, 256);
    // (3) layer-0 A convert
    asplit_k<<<(N * 128 / 4 + 255) / 256, 256>>>(feats, pa16, N * 128 / 4);
    // (4) layer-0 GEMM  <-- profiled launch
    gemm_mma<<<grid256, 256, SM_GEMM>>>(pa16, pwt, pxh, pals, pald,
                                        as0, ad0, N, 128, 256, 1);

    // --- CSR build (must complete before agg0) ---
    decode_count_k<<<ethreads, 256>>>(ei, NE, N);
    int nb1 = (N + 1023) / 1024;
    scan1_k<<<nb1, 1024>>>(pdeg, prp, pbs, N);
    scan2_k<<<1, 256>>>(pbs, nb1);
    scan3_k<<<(N + 255) / 256, 256>>>(prp, pbs, pcur, N, ET);
    fill_k<<<ethreads, 256>>>(ET);

    // --- layer 0 aggregation (writes fp16 A for layer 1) ---
    gat_agg_h<8, 32, 1><<<nwarps_b, 256>>>(pxh, pals, pald, prp, pcs,
                                           nullptr, pa16, b0, N, 1);

    // --- layer 1: 256 -> 8x32 ---
    wt_k<<<(256 * 256 + 255) / 256, 256>>>(W1, pwt + 1 * 65536, 256, 256);
    gemm_mma<<<grid256, 256, SM_GEMM>>>(pa16, pwt + 65536, pxh,
                                        pals, pald, as1, ad1, N, 256, 256, 1);
    gat_agg_h<8, 32, 1><<<nwarps_b, 256>>>(pxh, pals, pald, prp, pcs,
                                           nullptr, pa16, b1, N, 1);

    // --- layer 2: 256 -> 1x40 (al fused into GEMM epilogue, mode 2) ---
    wt_k<<<(40 * 256 + 255) / 256, 256>>>(W2, pwt + 2 * 65536, 256, 40);
    gemm_mma<<<grid40, 256, SM_GEMM>>>(pa16, pwt + 2 * 65536,
                                       pxh, pals, pald, as2, ad2, N, 256, 40, 2);
    gat_agg_h<1, 40, 0><<<nwarps_b, 256>>>(pxh, pals, pald, prp, pcs,
                                           out, nullptr, b2, N, 0);
}

// round 16
// speedup vs baseline: 1.1040x; 1.0543x over previous
#include <cuda_runtime.h>
#include <cuda_bf16.h>
#include <cuda_fp16.h>
#include <cstdint>

#define FIN     128
#define NNODES  100000
#define NEDGE   1600000
#define ETOTMAX (NEDGE + NNODES)

#define BM 256
#define BN 64
#define BK 32
#define BKP 40            // padded SMEM row length (fp16 elems) = 80 bytes
#define A_STG 20480       // 256 rows x 80 B
#define B_STG 5120        // 64 rows x 80 B
#define STG_BYTES (A_STG + B_STG)
#define NSTAGE 2
#define SM_GEMM (NSTAGE * STG_BYTES)

// ---------------- scratch (static device globals; no runtime allocation) ----
__device__ __half g_xh[(size_t)NNODES * 256];   // GEMM output (fp16)
__device__ __half g_a16[(size_t)NNODES * 256];  // GEMM A operand (fp16)
__device__ float g_als[NNODES * 8];
__device__ float g_ald[NNODES * 8];
__device__ int   g_deg[NNODES + 1];
__device__ int   g_rp[NNODES + 1];
__device__ int   g_cur[NNODES];
__device__ int   g_csrc[ETOTMAX];
__device__ int   g_bs[256];
__device__ int   g_is64;
__device__ __half g_wt[3][256 * 256];           // per-layer weight (fp16, [N,K])

// ======================= small PTX helpers ==================================
__device__ __forceinline__ uint32_t smem_to_u32(const void* p) {
    uint32_t a;
    asm("{ .reg .u64 t; cvta.to.shared.u64 t, %1; cvt.u32.u64 %0, t; }"
        : "=r"(a) : "l"(p));
    return a;
}
__device__ __forceinline__ void ldsm4(uint32_t* r, uint32_t addr) {
    asm volatile("ldmatrix.sync.aligned.m8n8.x4.shared.b16 {%0,%1,%2,%3}, [%4];"
                 : "=r"(r[0]), "=r"(r[1]), "=r"(r[2]), "=r"(r[3]) : "r"(addr));
}
__device__ __forceinline__ void mma_fp16(float* c, const uint32_t* a, const uint32_t* b) {
    asm volatile("mma.sync.aligned.m16n8k16.row.col.f32.f16.f16.f32 "
                 "{%0,%1,%2,%3}, {%4,%5,%6,%7}, {%8,%9}, {%0,%1,%2,%3};"
                 : "+f"(c[0]), "+f"(c[1]), "+f"(c[2]), "+f"(c[3])
                 : "r"(a[0]), "r"(a[1]), "r"(a[2]), "r"(a[3]), "r"(b[0]), "r"(b[1]));
}
__device__ __forceinline__ void cp16(uint32_t dst, const void* src, bool valid) {
    int sz = valid ? 16 : 0;
    asm volatile("cp.async.cg.shared.global [%0], [%1], 16, %2;"
                 :: "r"(dst), "l"(src), "r"(sz));
}
#define CP_COMMIT() asm volatile("cp.async.commit_group;" ::: "memory")
#define CP_WAIT(n)  asm volatile("cp.async.wait_group %0;" :: "n"(n) : "memory")

// ---------------- edge decode (inline, no scratch arrays) --------------------
__device__ __forceinline__ void decode_edge(const void* __restrict__ ei,
                                            int e, int ne, int& s, int& d) {
    if (e < ne) {
        if (g_is64) {
            const long long* p = (const long long*)ei;
            s = (int)p[e];
            d = (int)p[(size_t)ne + e];
        } else {
            const int* p = (const int*)ei;
            s = p[e];
            d = p[ne + e];
        }
    } else {
        s = e - ne; d = e - ne;
    }
}

// ------- detect edge dtype (block 0) + zero degree array (all blocks) -------
__global__ void detect_zero_k(const unsigned int* __restrict__ w,
                              int* __restrict__ deg, int n) {
    if (blockIdx.x == 0) {
        __shared__ int flag;
        if (threadIdx.x == 0) flag = 0;
        __syncthreads();
        int local = 0;
        for (int i = threadIdx.x; i < 2048; i += blockDim.x)
            if ((i & 1) && w[i]) local = 1;
        if (local) atomicOr(&flag, 1);
        __syncthreads();
        if (threadIdx.x == 0) g_is64 = flag ? 0 : 1;
    }
    for (int i = blockIdx.x * blockDim.x + threadIdx.x; i < n;
         i += gridDim.x * blockDim.x)
        deg[i] = 0;
}

__global__ void count_k(const void* __restrict__ ei, int ne, int n) {
    int e = blockIdx.x * blockDim.x + threadIdx.x;
    if (e >= ne + n) return;
    int s, d;
    decode_edge(ei, e, ne, s, d);
    atomicAdd(&g_deg[d], 1);
}

// ---------------- CSR build --------------------------------------------------
__global__ void scan1_k(const int* __restrict__ deg, int* __restrict__ ex,
                        int* __restrict__ bsums, int n) {
    __shared__ int sh[1024];
    int i = blockIdx.x * 1024 + threadIdx.x;
    int v = (i < n) ? deg[i] : 0;
    sh[threadIdx.x] = v;
    __syncthreads();
    for (int off = 1; off < 1024; off <<= 1) {
        int t = (threadIdx.x >= off) ? sh[threadIdx.x - off] : 0;
        __syncthreads();
        sh[threadIdx.x] += t;
        __syncthreads();
    }
    if (i < n) ex[i] = sh[threadIdx.x] - v;
    if (threadIdx.x == 1023) bsums[blockIdx.x] = sh[1023];
}
__global__ void scan2_k(int* __restrict__ bsums, int nb) {
    __shared__ int sh[256];
    int v = (threadIdx.x < nb) ? bsums[threadIdx.x] : 0;
    sh[threadIdx.x] = v;
    __syncthreads();
    for (int off = 1; off < 256; off <<= 1) {
        int t = (threadIdx.x >= off) ? sh[threadIdx.x - off] : 0;
        __syncthreads();
        sh[threadIdx.x] += t;
        __syncthreads();
    }
    if (threadIdx.x < nb) bsums[threadIdx.x] = sh[threadIdx.x] - v;
}
__global__ void scan3_k(int* __restrict__ rp, const int* __restrict__ bsums,
                        int* __restrict__ cur, int n, int total) {
    int i = blockIdx.x * blockDim.x + threadIdx.x;
    if (i < n) {
        rp[i] += bsums[i >> 10];
        cur[i] = 0;
    }
    if (i == 0) rp[n] = total;
}
__global__ void fill_k(const void* __restrict__ ei, int ne, int n) {
    int e = blockIdx.x * blockDim.x + threadIdx.x;
    if (e >= ne + n) return;
    int s, d;
    decode_edge(ei, e, ne, s, d);
    int slot = g_rp[d] + atomicAdd(&g_cur[d], 1);
    g_csrc[slot] = s;
}

// ---------------- W transpose -> fp16 [N,K] (all 3 layers in one) -----------
__global__ void wt_all_k(const float* __restrict__ W0,
                         const float* __restrict__ W1,
                         const float* __restrict__ W2,
                         __half* __restrict__ o) {
    int idx = blockIdx.x * blockDim.x + threadIdx.x;
    // segment 0: 256x128 (K=128, NT=256) -> o[0 .. 32768)
    // segment 1: 256x256 (K=256, NT=256) -> o[65536 .. 131072)
    // segment 2: 256x40  (K=256, NT=40)  -> o[131072 .. 141312)
    if (idx < 32768) {
        int n = idx >> 7, k = idx & 127;
        o[idx] = __float2half_rn(W0[(size_t)k * 256 + n]);
    } else if (idx < 32768 + 65536) {
        int j = idx - 32768;
        int n = j >> 8, k = j & 255;
        o[65536 + j] = __float2half_rn(W1[(size_t)k * 256 + n]);
    } else if (idx < 32768 + 65536 + 40 * 256) {
        int j = idx - (32768 + 65536);
        int n = j >> 8, k = j & 255;
        o[131072 + j] = __float2half_rn(W2[(size_t)k * 40 + n]);
    }
}

// ---------------- A convert: fp32 -> fp16 (layer 0 input only) --------------
__global__ void asplit_k(const float* __restrict__ A, __half* __restrict__ o,
                         int total4) {
    int i = blockIdx.x * blockDim.x + threadIdx.x;
    if (i >= total4) return;
    float4 v = reinterpret_cast<const float4*>(A)[i];
    uint2 p;
    __half2 t0 = __floats2half2_rn(v.x, v.y);
    __half2 t1 = __floats2half2_rn(v.z, v.w);
    p.x = *reinterpret_cast<uint32_t*>(&t0);
    p.y = *reinterpret_cast<uint32_t*>(&t1);
    reinterpret_cast<uint2*>(o)[i] = p;
}

// ---------------- HMMA fp16 GEMM (BM=256, warp 32x64, 2-stage cp.async) ------
__device__ __forceinline__ void stage_cp(
    const __half* __restrict__ A, const __half* __restrict__ B,
    uint32_t sbase, int ctaM, int ctaN, int kc, int M, int NT, int Kdim, int t) {
    {
        int r = t;
        int row = ctaM + r;
        bool ok = row < M;
        const __half* p = A + (size_t)row * Kdim + kc;
        uint32_t d = sbase + (uint32_t)(r * BKP) * 2;
#pragma unroll
        for (int j = 0; j < 4; j++)
            cp16(d + j * 16, p + j * 8, ok);
    }
    {
        int n = t >> 2, j = t & 3;
        int gn = ctaN + n;
        bool ok = gn < NT;
        const __half* q = B + (size_t)gn * Kdim + kc + j * 8;
        uint32_t d = sbase + A_STG + (uint32_t)(n * BKP + j * 8) * 2;
        cp16(d, q, ok);
    }
}

__global__ __launch_bounds__(256, 2)
void gemm_mma(const __half* __restrict__ A,
              const __half* __restrict__ B,
              __half* __restrict__ C,
              float* __restrict__ als, float* __restrict__ ald,
              const float* __restrict__ a_src, const float* __restrict__ a_dst,
              int M, int Kdim, int NT, int fuse_al) {
    extern __shared__ char smem[];
    const int t = threadIdx.x;
    const int wid = t >> 5, lane = t & 31;
    const int ctaM = blockIdx.y * BM;
    const int ctaN = blockIdx.x * BN;
    const uint32_t sb = smem_to_u32(smem);

    float acc[2][8][4];
#pragma unroll
    for (int i = 0; i < 2; i++)
#pragma unroll
        for (int j = 0; j < 8; j++)
#pragma unroll
            for (int k = 0; k < 4; k++) acc[i][j][k] = 0.f;

    const int nk = Kdim / BK;

    stage_cp(A, B, sb, ctaM, ctaN, 0, M, NT, Kdim, t);
    CP_COMMIT();

    for (int i = 0; i < nk; i++) {
        if (i + 1 < nk) {
            stage_cp(A, B, sb + ((i + 1) & 1) * STG_BYTES,
                     ctaM, ctaN, (i + 1) * BK, M, NT, Kdim, t);
            CP_COMMIT();
            CP_WAIT(1);
        } else {
            CP_WAIT(0);
        }
        __syncthreads();

        const uint32_t sBase = sb + (uint32_t)((i & 1) * STG_BYTES);
#pragma unroll
        for (int kk = 0; kk < 2; kk++) {
            const int kb = kk * 16;
            uint32_t ah[2][4];
#pragma unroll
            for (int mt = 0; mt < 2; mt++) {
                int row_in = wid * 32 + mt * 16 + (lane & 15);
                int koff = kb + ((lane >> 4) << 3);
                uint32_t off = (uint32_t)(row_in * BKP + koff) * 2;
                ldsm4(ah[mt], sBase + off);
            }
            uint32_t bh[8][2];
#pragma unroll
            for (int nt2 = 0; nt2 < 4; nt2++) {
                int n_in = nt2 * 16 + ((lane >> 4) << 3) + (lane & 7);
                int koff = kb + ((lane >> 3) & 1) * 8;
                uint32_t off = (uint32_t)(n_in * BKP + koff) * 2;
                uint32_t r[4];
                ldsm4(r, sBase + A_STG + off);
                bh[nt2 * 2][0] = r[0]; bh[nt2 * 2][1] = r[1];
                bh[nt2 * 2 + 1][0] = r[2]; bh[nt2 * 2 + 1][1] = r[3];
            }
#pragma unroll
            for (int mt = 0; mt < 2; mt++)
#pragma unroll
                for (int nt = 0; nt < 8; nt++)
                    mma_fp16(acc[mt][nt], ah[mt], bh[nt]);
        }
        __syncthreads();
    }

    // ---- epilogue: write C (fp16) + fused attention logits ----
    const int grp = lane >> 2, q = lane & 3;
#pragma unroll
    for (int mt = 0; mt < 2; mt++) {
#pragma unroll
        for (int half = 0; half < 2; half++) {
            int row = ctaM + wid * 32 + mt * 16 + grp + half * 8;
            float as_tot = 0.f, ad_tot = 0.f;
#pragma unroll
            for (int hg = 0; hg < 2; hg++) {
                float as_p = 0.f, ad_p = 0.f;
#pragma unroll
                for (int nt4 = 0; nt4 < 4; nt4++) {
                    int nt = hg * 4 + nt4;
                    int gcol = ctaN + nt * 8 + q * 2;
                    float v0 = acc[mt][nt][half * 2 + 0];
                    float v1 = acc[mt][nt][half * 2 + 1];
                    bool okc = gcol < NT;
                    if (row < M && okc)
                        *(__half2*)&C[(size_t)row * NT + gcol] = __floats2half2_rn(v0, v1);
                    if (fuse_al && okc) {
                        as_p += v0 * a_src[gcol] + v1 * a_src[gcol + 1];
                        ad_p += v0 * a_dst[gcol] + v1 * a_dst[gcol + 1];
                    }
                }
                if (fuse_al == 1) {
                    as_p += __shfl_xor_sync(0xffffffffu, as_p, 1);
                    as_p += __shfl_xor_sync(0xffffffffu, as_p, 2);
                    ad_p += __shfl_xor_sync(0xffffffffu, ad_p, 1);
                    ad_p += __shfl_xor_sync(0xffffffffu, ad_p, 2);
                    int head = (ctaN + hg * 32) >> 5;
                    if (q == 0 && row < M) {
                        als[(size_t)row * 8 + head] = as_p;
                        ald[(size_t)row * 8 + head] = ad_p;
                    }
                } else {
                    as_tot += as_p;
                    ad_tot += ad_p;
                }
            }
            if (fuse_al == 2) {
                as_tot += __shfl_xor_sync(0xffffffffu, as_tot, 1);
                as_tot += __shfl_xor_sync(0xffffffffu, as_tot, 2);
                ad_tot += __shfl_xor_sync(0xffffffffu, ad_tot, 1);
                ad_tot += __shfl_xor_sync(0xffffffffu, ad_tot, 2);
                if (q == 0 && row < M) {
                    als[row] = as_tot;
                    ald[row] = ad_tot;
                }
            }
        }
    }
}

// ------- fused SINGLE-PASS softmax + aggregate + bias(+elu): warp per dst ---
// 2-edge unrolled main loop for memory-level parallelism. (H=8, C=32 layers)
template <int H, int C, int OUTMODE>
__global__ void gat_agg_h(const __half* __restrict__ x,
                          const float* __restrict__ als,
                          const float* __restrict__ ald,
                          const int* __restrict__ rp,
                          const int* __restrict__ cs,
                          float* __restrict__ out,
                          __half* __restrict__ oh,
                          const float* __restrict__ bias,
                          int Nn, int do_elu) {
    constexpr int HC = H * C;
    int n = (blockIdx.x * blockDim.x + threadIdx.x) >> 5;
    int lane = threadIdx.x & 31;
    if (n >= Nn) return;

    int start = rp[n], end = rp[n + 1];
    float aldv = (lane < H) ? ald[n * H + lane] : 0.f;

    const int col0 = lane * 8;
    const bool act = col0 < HC;
    const int alane = act ? (col0 / C) : 0;
    float acc[8];
#pragma unroll
    for (int i = 0; i < 8; i++) acc[i] = 0.f;
    float sacc = 0.f;

    int k = start;
    for (; k + 1 < end; k += 2) {
        int s0 = cs[k], s1 = cs[k + 1];
        float e0 = 0.f, e1 = 0.f;
        if (lane < H) {
            float v0 = als[s0 * H + lane] + aldv;
            float v1 = als[s1 * H + lane] + aldv;
            v0 = v0 > 0.f ? v0 : 0.2f * v0;
            v1 = v1 > 0.f ? v1 : 0.2f * v1;
            e0 = __expf(v0);
            e1 = __expf(v1);
            sacc += e0 + e1;
        }
        float a0 = __shfl_sync(0xffffffffu, e0, alane);
        float a1 = __shfl_sync(0xffffffffu, e1, alane);
        if (act) {
            uint4 w0 = *(const uint4*)(x + (size_t)s0 * HC + col0);
            uint4 w1 = *(const uint4*)(x + (size_t)s1 * HC + col0);
            float2 f;
            f = __half22float2(*(__half2*)&w0.x); acc[0] += f.x * a0; acc[1] += f.y * a0;
            f = __half22float2(*(__half2*)&w0.y); acc[2] += f.x * a0; acc[3] += f.y * a0;
            f = __half22float2(*(__half2*)&w0.z); acc[4] += f.x * a0; acc[5] += f.y * a0;
            f = __half22float2(*(__half2*)&w0.w); acc[6] += f.x * a0; acc[7] += f.y * a0;
            f = __half22float2(*(__half2*)&w1.x); acc[0] += f.x * a1; acc[1] += f.y * a1;
            f = __half22float2(*(__half2*)&w1.y); acc[2] += f.x * a1; acc[3] += f.y * a1;
            f = __half22float2(*(__half2*)&w1.z); acc[4] += f.x * a1; acc[5] += f.y * a1;
            f = __half22float2(*(__half2*)&w1.w); acc[6] += f.x * a1; acc[7] += f.y * a1;
        }
    }
    if (k < end) {
        int s0 = cs[k];
        float e0 = 0.f;
        if (lane < H) {
            float v0 = als[s0 * H + lane] + aldv;
            v0 = v0 > 0.f ? v0 : 0.2f * v0;
            e0 = __expf(v0);
            sacc += e0;
        }
        float a0 = __shfl_sync(0xffffffffu, e0, alane);
        if (act) {
            uint4 w0 = *(const uint4*)(x + (size_t)s0 * HC + col0);
            float2 f;
            f = __half22float2(*(__half2*)&w0.x); acc[0] += f.x * a0; acc[1] += f.y * a0;
            f = __half22float2(*(__half2*)&w0.y); acc[2] += f.x * a0; acc[3] += f.y * a0;
            f = __half22float2(*(__half2*)&w0.z); acc[4] += f.x * a0; acc[5] += f.y * a0;
            f = __half22float2(*(__half2*)&w0.w); acc[6] += f.x * a0; acc[7] += f.y * a0;
        }
    }

    float inv_s = (lane < H && sacc > 0.f) ? __frcp_rn(sacc) : 0.f;
    float scale = __shfl_sync(0xffffffffu, inv_s, alane);

    if (act) {
        float o[8];
#pragma unroll
        for (int i = 0; i < 8; i++) {
            float v = acc[i] * scale + bias[col0 + i];
            if (do_elu) v = v > 0.f ? v : expm1f(v);
            o[i] = v;
        }
        if (OUTMODE == 0) {
            float* od = out + (size_t)n * HC + col0;
            *(float4*)(od)     = make_float4(o[0], o[1], o[2], o[3]);
            *(float4*)(od + 4) = make_float4(o[4], o[5], o[6], o[7]);
        } else {
            uint4 p;
            __half2 t0 = __floats2half2_rn(o[0], o[1]);
            __half2 t1 = __floats2half2_rn(o[2], o[3]);
            __half2 t2 = __floats2half2_rn(o[4], o[5]);
            __half2 t3 = __floats2half2_rn(o[6], o[7]);
            p.x = *(uint32_t*)&t0; p.y = *(uint32_t*)&t1;
            p.z = *(uint32_t*)&t2; p.w = *(uint32_t*)&t3;
            *(uint4*)(oh + (size_t)n * HC + col0) = p;
        }
    }
}

// ------- layer-2 aggregation: H=1, C=40, 4 nodes per warp (8-lane groups) ---
__global__ void gat_agg2_k(const __half* __restrict__ x,
                           const float* __restrict__ als,
                           const float* __restrict__ ald,
                           const int* __restrict__ rp,
                           const int* __restrict__ cs,
                           float* __restrict__ out,
                           const float* __restrict__ bias,
                           int Nn) {
    int warp = (blockIdx.x * blockDim.x + threadIdx.x) >> 5;
    int lane = threadIdx.x & 31;
    int g = lane >> 3, sl = lane & 7;
    int n = warp * 4 + g;
    bool nok = n < Nn;

    int start = nok ? rp[n] : 0;
    int end   = nok ? rp[n + 1] : 0;
    int cnt = end - start;
    // max count across the 4 groups (converged loop)
    int mc = cnt;
#pragma unroll
    for (int off = 8; off < 32; off <<= 1)
        mc = max(mc, __shfl_xor_sync(0xffffffffu, mc, off));

    float aldv = nok ? ald[n] : 0.f;
    const int col0 = sl * 8;
    const bool act = nok && col0 < 40;
    float acc[8];
#pragma unroll
    for (int i = 0; i < 8; i++) acc[i] = 0.f;
    float sacc = 0.f;

    for (int k = 0; k < mc; k++) {
        bool ok = k < cnt;
        int src = ok ? cs[start + k] : 0;
        float e = 0.f;
        if (sl == 0 && ok) {
            float v = als[src] + aldv;
            v = v > 0.f ? v : 0.2f * v;
            e = __expf(v);
            sacc += e;
        }
        float a = __shfl_sync(0xffffffffu, e, g * 8);
        if (act && ok) {
            uint4 w0 = *(const uint4*)(x + (size_t)src * 40 + col0);
            float2 f;
            f = __half22float2(*(__half2*)&w0.x); acc[0] += f.x * a; acc[1] += f.y * a;
            f = __half22float2(*(__half2*)&w0.y); acc[2] += f.x * a; acc[3] += f.y * a;
            f = __half22float2(*(__half2*)&w0.z); acc[4] += f.x * a; acc[5] += f.y * a;
            f = __half22float2(*(__half2*)&w0.w); acc[6] += f.x * a; acc[7] += f.y * a;
        }
    }

    float inv_s = (sl == 0 && sacc > 0.f) ? __frcp_rn(sacc) : 0.f;
    float scale = __shfl_sync(0xffffffffu, inv_s, g * 8);

    if (act) {
        float o[8];
#pragma unroll
        for (int i = 0; i < 8; i++)
            o[i] = acc[i] * scale + bias[col0 + i];
        float* od = out + (size_t)n * 40 + col0;
        *(float4*)(od)     = make_float4(o[0], o[1], o[2], o[3]);
        *(float4*)(od + 4) = make_float4(o[4], o[5], o[6], o[7]);
    }
}

// ---------------- launcher (single stream — graph-capture friendly) ---------
extern "C" void kernel_launch(void* const* d_in, const int* in_sizes, int n_in,
                              void* d_out, int out_size) {
    const float* feats = (const float*)d_in[0];
    const void*  ei    = d_in[1];
    const float* W0  = (const float*)d_in[2];
    const float* as0 = (const float*)d_in[3];
    const float* ad0 = (const float*)d_in[4];
    const float* b0  = (const float*)d_in[5];
    const float* W1  = (const float*)d_in[6];
    const float* as1 = (const float*)d_in[7];
    const float* ad1 = (const float*)d_in[8];
    const float* b1  = (const float*)d_in[9];
    const float* W2  = (const float*)d_in[10];
    const float* as2 = (const float*)d_in[11];
    const float* ad2 = (const float*)d_in[12];
    const float* b2  = (const float*)d_in[13];

    int N  = in_sizes[0] / FIN;
    int NE = in_sizes[1] / 2;
    int ET = NE + N;
    float* out = (float*)d_out;
    (void)n_in; (void)out_size;

    __half *pxh, *pa16, *pwt;
    float *pals, *pald;
    int *pdeg, *prp, *pcur, *pcs, *pbs;
    cudaGetSymbolAddress((void**)&pxh,  g_xh);
    cudaGetSymbolAddress((void**)&pa16, g_a16);
    cudaGetSymbolAddress((void**)&pals, g_als);
    cudaGetSymbolAddress((void**)&pald, g_ald);
    cudaGetSymbolAddress((void**)&pdeg, g_deg);
    cudaGetSymbolAddress((void**)&prp,  g_rp);
    cudaGetSymbolAddress((void**)&pcur, g_cur);
    cudaGetSymbolAddress((void**)&pcs,  g_csrc);
    cudaGetSymbolAddress((void**)&pbs,  g_bs);
    cudaGetSymbolAddress((void**)&pwt,  g_wt);

    cudaFuncSetAttribute(gemm_mma, cudaFuncAttributeMaxDynamicSharedMemorySize, SM_GEMM);

    int ethreads = (ET + 255) / 256;
    int nwarps_b = (N * 32 + 255) / 256;
    int nwarps_q = ((N + 3) / 4 * 32 + 255) / 256;
    dim3 grid256(4, (N + BM - 1) / BM);
    dim3 grid40(1, (N + BM - 1) / BM);

    // (1) dtype detect + zero(deg)
    detect_zero_k<<<256, 256>>>((const unsigned int*)ei, pdeg, N + 1);
    // (2) all weights (one kernel)
    wt_all_k<<<(32768 + 65536 + 40 * 256 + 255) / 256, 256>>>(W0, W1, W2, pwt);
    // (3) layer-0 A convert
    asplit_k<<<(N * 128 / 4 + 255) / 256, 256>>>(feats, pa16, N * 128 / 4);
    // (4) layer-0 GEMM  <-- profiled launch
    gemm_mma<<<grid256, 256, SM_GEMM>>>(pa16, pwt, pxh, pals, pald,
                                        as0, ad0, N, 128, 256, 1);

    // --- CSR build (inline edge decode; must complete before agg0) ---
    count_k<<<ethreads, 256>>>(ei, NE, N);
    int nb1 = (N + 1023) / 1024;
    scan1_k<<<nb1, 1024>>>(pdeg, prp, pbs, N);
    scan2_k<<<1, 256>>>(pbs, nb1);
    scan3_k<<<(N + 255) / 256, 256>>>(prp, pbs, pcur, N, ET);
    fill_k<<<ethreads, 256>>>(ei, NE, N);

    // --- layer 0 aggregation (writes fp16 A for layer 1) ---
    gat_agg_h<8, 32, 1><<<nwarps_b, 256>>>(pxh, pals, pald, prp, pcs,
                                           nullptr, pa16, b0, N, 1);

    // --- layer 1: 256 -> 8x32 ---
    gemm_mma<<<grid256, 256, SM_GEMM>>>(pa16, pwt + 65536, pxh,
                                        pals, pald, as1, ad1, N, 256, 256, 1);
    gat_agg_h<8, 32, 1><<<nwarps_b, 256>>>(pxh, pals, pald, prp, pcs,
                                           nullptr, pa16, b1, N, 1);

    // --- layer 2: 256 -> 1x40 (al fused into GEMM epilogue, mode 2) ---
    gemm_mma<<<grid40, 256, SM_GEMM>>>(pa16, pwt + 131072,
                                       pxh, pals, pald, as2, ad2, N, 256, 40, 2);
    gat_agg2_k<<<nwarps_q, 256>>>(pxh, pals, pald, prp, pcs, out, b2, N);
}

// round 17
// speedup vs baseline: 1.1300x; 1.0236x over previous
#include <cuda_runtime.h>
#include <cuda_bf16.h>
#include <cuda_fp16.h>
#include <cstdint>

#define FIN     128
#define NNODES  100000
#define NEDGE   1600000
#define ETOTMAX (NEDGE + NNODES)

#define BM 256
#define BN 64

// ---------------- scratch (static device globals; no runtime allocation) ----
__device__ __half g_xh[(size_t)NNODES * 256];   // GEMM output (fp16)
__device__ __half g_a16[(size_t)NNODES * 256];  // GEMM A operand (fp16)
__device__ float g_als[NNODES * 8];
__device__ float g_ald[NNODES * 8];
__device__ int   g_deg[NNODES + 1];
__device__ int   g_rp[NNODES + 1];
__device__ int   g_cur[NNODES];
__device__ int   g_csrc[ETOTMAX];
__device__ int   g_bs[256];
__device__ int   g_is64;
__device__ __half g_wt[3][256 * 256];           // per-layer weight (fp16, [N,K])

// ======================= small PTX helpers ==================================
__device__ __forceinline__ uint32_t smem_to_u32(const void* p) {
    uint32_t a;
    asm("{ .reg .u64 t; cvta.to.shared.u64 t, %1; cvt.u32.u64 %0, t; }"
        : "=r"(a) : "l"(p));
    return a;
}
__device__ __forceinline__ void ldsm4(uint32_t* r, uint32_t addr) {
    asm volatile("ldmatrix.sync.aligned.m8n8.x4.shared.b16 {%0,%1,%2,%3}, [%4];"
                 : "=r"(r[0]), "=r"(r[1]), "=r"(r[2]), "=r"(r[3]) : "r"(addr));
}
__device__ __forceinline__ void mma_fp16(float* c, const uint32_t* a, const uint32_t* b) {
    asm volatile("mma.sync.aligned.m16n8k16.row.col.f32.f16.f16.f32 "
                 "{%0,%1,%2,%3}, {%4,%5,%6,%7}, {%8,%9}, {%0,%1,%2,%3};"
                 : "+f"(c[0]), "+f"(c[1]), "+f"(c[2]), "+f"(c[3])
                 : "r"(a[0]), "r"(a[1]), "r"(a[2]), "r"(a[3]), "r"(b[0]), "r"(b[1]));
}
__device__ __forceinline__ void cp16(uint32_t dst, const void* src, bool valid) {
    int sz = valid ? 16 : 0;
    asm volatile("cp.async.cg.shared.global [%0], [%1], 16, %2;"
                 :: "r"(dst), "l"(src), "r"(sz));
}
#define CP_COMMIT() asm volatile("cp.async.commit_group;" ::: "memory")
#define CP_WAIT(n)  asm volatile("cp.async.wait_group %0;" :: "n"(n) : "memory")

// ---------------- edge decode (inline, no scratch arrays) --------------------
__device__ __forceinline__ void decode_edge(const void* __restrict__ ei,
                                            int e, int ne, int& s, int& d) {
    if (e < ne) {
        if (g_is64) {
            const long long* p = (const long long*)ei;
            s = (int)p[e];
            d = (int)p[(size_t)ne + e];
        } else {
            const int* p = (const int*)ei;
            s = p[e];
            d = p[ne + e];
        }
    } else {
        s = e - ne; d = e - ne;
    }
}

// ------- detect edge dtype (block 0) + zero degree array (all blocks) -------
__global__ void detect_zero_k(const unsigned int* __restrict__ w,
                              int* __restrict__ deg, int n) {
    if (blockIdx.x == 0) {
        __shared__ int flag;
        if (threadIdx.x == 0) flag = 0;
        __syncthreads();
        int local = 0;
        for (int i = threadIdx.x; i < 2048; i += blockDim.x)
            if ((i & 1) && w[i]) local = 1;
        if (local) atomicOr(&flag, 1);
        __syncthreads();
        if (threadIdx.x == 0) g_is64 = flag ? 0 : 1;
    }
    for (int i = blockIdx.x * blockDim.x + threadIdx.x; i < n;
         i += gridDim.x * blockDim.x)
        deg[i] = 0;
}

__global__ void count_k(const void* __restrict__ ei, int ne, int n) {
    int e = blockIdx.x * blockDim.x + threadIdx.x;
    if (e >= ne + n) return;
    int s, d;
    decode_edge(ei, e, ne, s, d);
    atomicAdd(&g_deg[d], 1);
}

// ---------------- CSR build --------------------------------------------------
__global__ void scan1_k(const int* __restrict__ deg, int* __restrict__ ex,
                        int* __restrict__ bsums, int n) {
    __shared__ int sh[1024];
    int i = blockIdx.x * 1024 + threadIdx.x;
    int v = (i < n) ? deg[i] : 0;
    sh[threadIdx.x] = v;
    __syncthreads();
    for (int off = 1; off < 1024; off <<= 1) {
        int t = (threadIdx.x >= off) ? sh[threadIdx.x - off] : 0;
        __syncthreads();
        sh[threadIdx.x] += t;
        __syncthreads();
    }
    if (i < n) ex[i] = sh[threadIdx.x] - v;
    if (threadIdx.x == 1023) bsums[blockIdx.x] = sh[1023];
}
__global__ void scan2_k(int* __restrict__ bsums, int nb) {
    __shared__ int sh[256];
    int v = (threadIdx.x < nb) ? bsums[threadIdx.x] : 0;
    sh[threadIdx.x] = v;
    __syncthreads();
    for (int off = 1; off < 256; off <<= 1) {
        int t = (threadIdx.x >= off) ? sh[threadIdx.x - off] : 0;
        __syncthreads();
        sh[threadIdx.x] += t;
        __syncthreads();
    }
    if (threadIdx.x < nb) bsums[threadIdx.x] = sh[threadIdx.x] - v;
}
__global__ void scan3_k(int* __restrict__ rp, const int* __restrict__ bsums,
                        int* __restrict__ cur, int n, int total) {
    int i = blockIdx.x * blockDim.x + threadIdx.x;
    if (i < n) {
        rp[i] += bsums[i >> 10];
        cur[i] = 0;
    }
    if (i == 0) rp[n] = total;
}
__global__ void fill_k(const void* __restrict__ ei, int ne, int n) {
    int e = blockIdx.x * blockDim.x + threadIdx.x;
    if (e >= ne + n) return;
    int s, d;
    decode_edge(ei, e, ne, s, d);
    int slot = g_rp[d] + atomicAdd(&g_cur[d], 1);
    g_csrc[slot] = s;
}

// ---------------- W transpose -> fp16 [N,K] (all 3 layers in one) -----------
__global__ void wt_all_k(const float* __restrict__ W0,
                         const float* __restrict__ W1,
                         const float* __restrict__ W2,
                         __half* __restrict__ o) {
    int idx = blockIdx.x * blockDim.x + threadIdx.x;
    if (idx < 32768) {
        int n = idx >> 7, k = idx & 127;
        o[idx] = __float2half_rn(W0[(size_t)k * 256 + n]);
    } else if (idx < 32768 + 65536) {
        int j = idx - 32768;
        int n = j >> 8, k = j & 255;
        o[65536 + j] = __float2half_rn(W1[(size_t)k * 256 + n]);
    } else if (idx < 32768 + 65536 + 40 * 256) {
        int j = idx - (32768 + 65536);
        int n = j >> 8, k = j & 255;
        o[131072 + j] = __float2half_rn(W2[(size_t)k * 40 + n]);
    }
}

// ---------------- A convert: fp32 -> fp16 (layer 0 input only) --------------
__global__ void asplit_k(const float* __restrict__ A, __half* __restrict__ o,
                         int total4) {
    int i = blockIdx.x * blockDim.x + threadIdx.x;
    if (i >= total4) return;
    float4 v = reinterpret_cast<const float4*>(A)[i];
    uint2 p;
    __half2 t0 = __floats2half2_rn(v.x, v.y);
    __half2 t1 = __floats2half2_rn(v.z, v.w);
    p.x = *reinterpret_cast<uint32_t*>(&t0);
    p.y = *reinterpret_cast<uint32_t*>(&t1);
    reinterpret_cast<uint2*>(o)[i] = p;
}

// ---------------- A-stationary HMMA fp16 GEMM --------------------------------
// CTA: 256 M-rows, full A panel (256 x K fp16) resident in SMEM (loaded once),
// loops over N in 64-col blocks with double-buffered B tiles.
// SMEM row stride KP = K+8 halfs (bank-conflict-free for ldsm).
__global__ __launch_bounds__(256, 1)
void gemm_as(const __half* __restrict__ A,
             const __half* __restrict__ B,
             __half* __restrict__ C,
             float* __restrict__ als, float* __restrict__ ald,
             const float* __restrict__ a_src, const float* __restrict__ a_dst,
             int M, int Kdim, int NT, int fuse_al) {
    extern __shared__ char smem[];
    const int t = threadIdx.x;
    const int wid = t >> 5, lane = t & 31;
    const int ctaM = blockIdx.y * BM;
    const int KP = Kdim + 8;
    const uint32_t sA = smem_to_u32(smem);
    const uint32_t A_BYTES = (uint32_t)(BM * KP) * 2;
    const uint32_t B_BYTES = (uint32_t)(BN * KP) * 2;

    // ---- load full A panel (once) ----
    {
        int row = t;
        bool ok = (ctaM + row) < M;
        const __half* p = A + (size_t)(ctaM + row) * Kdim;
        uint32_t d = sA + (uint32_t)(row * KP) * 2;
        for (int j = 0; j < Kdim; j += 8)
            cp16(d + j * 2, p + j, ok);
    }
    CP_COMMIT();

    const int nblks = (NT + BN - 1) / BN;
    const int cpt = Kdim / 32;              // 16B chunks per thread for B tile

    // ---- load B block 0 ----
    {
        int n = t >> 2;
        int gn = n;                         // nb = 0
        bool ok = gn < NT;
        const __half* q = B + (size_t)gn * Kdim + (t & 3) * cpt * 8;
        uint32_t d = sA + A_BYTES + (uint32_t)(n * KP + (t & 3) * cpt * 8) * 2;
        for (int m = 0; m < cpt; m++)
            cp16(d + m * 16, q + m * 8, ok);
    }
    CP_COMMIT();
    CP_WAIT(0);
    __syncthreads();

    const int grp = lane >> 2, q4 = lane & 3;

    for (int nb = 0; nb < nblks; nb++) {
        // prefetch next B block into the other buffer
        if (nb + 1 < nblks) {
            int n = t >> 2;
            int gn = (nb + 1) * BN + n;
            bool ok = gn < NT;
            const __half* q = B + (size_t)gn * Kdim + (t & 3) * cpt * 8;
            uint32_t d = sA + A_BYTES + ((nb + 1) & 1) * B_BYTES
                       + (uint32_t)(n * KP + (t & 3) * cpt * 8) * 2;
            for (int m = 0; m < cpt; m++)
                cp16(d + m * 16, q + m * 8, ok);
            CP_COMMIT();
        }

        const uint32_t sB = sA + A_BYTES + (nb & 1) * B_BYTES;
        const int ctaN = nb * BN;

        float acc[2][8][4];
#pragma unroll
        for (int i = 0; i < 2; i++)
#pragma unroll
            for (int j = 0; j < 8; j++)
#pragma unroll
                for (int k = 0; k < 4; k++) acc[i][j][k] = 0.f;

        // full-K compute from SMEM
        for (int kk = 0; kk < Kdim / 16; kk++) {
            const int kb = kk * 16;
            uint32_t ah[2][4];
#pragma unroll
            for (int mt = 0; mt < 2; mt++) {
                int row_in = wid * 32 + mt * 16 + (lane & 15);
                int koff = kb + ((lane >> 4) << 3);
                ldsm4(ah[mt], sA + (uint32_t)(row_in * KP + koff) * 2);
            }
            uint32_t bh[8][2];
#pragma unroll
            for (int nt2 = 0; nt2 < 4; nt2++) {
                int n_in = nt2 * 16 + ((lane >> 4) << 3) + (lane & 7);
                int koff = kb + ((lane >> 3) & 1) * 8;
                uint32_t r[4];
                ldsm4(r, sB + (uint32_t)(n_in * KP + koff) * 2);
                bh[nt2 * 2][0] = r[0]; bh[nt2 * 2][1] = r[1];
                bh[nt2 * 2 + 1][0] = r[2]; bh[nt2 * 2 + 1][1] = r[3];
            }
#pragma unroll
            for (int mt = 0; mt < 2; mt++)
#pragma unroll
                for (int nt = 0; nt < 8; nt++)
                    mma_fp16(acc[mt][nt], ah[mt], bh[nt]);
        }

        // ---- epilogue for this N-block ----
#pragma unroll
        for (int mt = 0; mt < 2; mt++) {
#pragma unroll
            for (int half = 0; half < 2; half++) {
                int row = ctaM + wid * 32 + mt * 16 + grp + half * 8;
                float as_tot = 0.f, ad_tot = 0.f;
#pragma unroll
                for (int hg = 0; hg < 2; hg++) {
                    float as_p = 0.f, ad_p = 0.f;
#pragma unroll
                    for (int nt4 = 0; nt4 < 4; nt4++) {
                        int nt = hg * 4 + nt4;
                        int gcol = ctaN + nt * 8 + q4 * 2;
                        float v0 = acc[mt][nt][half * 2 + 0];
                        float v1 = acc[mt][nt][half * 2 + 1];
                        bool okc = gcol < NT;
                        if (row < M && okc)
                            *(__half2*)&C[(size_t)row * NT + gcol] =
                                __floats2half2_rn(v0, v1);
                        if (fuse_al && okc) {
                            as_p += v0 * a_src[gcol] + v1 * a_src[gcol + 1];
                            ad_p += v0 * a_dst[gcol] + v1 * a_dst[gcol + 1];
                        }
                    }
                    if (fuse_al == 1) {
                        as_p += __shfl_xor_sync(0xffffffffu, as_p, 1);
                        as_p += __shfl_xor_sync(0xffffffffu, as_p, 2);
                        ad_p += __shfl_xor_sync(0xffffffffu, ad_p, 1);
                        ad_p += __shfl_xor_sync(0xffffffffu, ad_p, 2);
                        int head = (ctaN + hg * 32) >> 5;
                        if (q4 == 0 && row < M) {
                            als[(size_t)row * 8 + head] = as_p;
                            ald[(size_t)row * 8 + head] = ad_p;
                        }
                    } else {
                        as_tot += as_p;
                        ad_tot += ad_p;
                    }
                }
                if (fuse_al == 2) {
                    as_tot += __shfl_xor_sync(0xffffffffu, as_tot, 1);
                    as_tot += __shfl_xor_sync(0xffffffffu, as_tot, 2);
                    ad_tot += __shfl_xor_sync(0xffffffffu, ad_tot, 1);
                    ad_tot += __shfl_xor_sync(0xffffffffu, ad_tot, 2);
                    if (q4 == 0 && row < M) {
                        als[row] = as_tot;
                        ald[row] = ad_tot;
                    }
                }
            }
        }

        if (nb + 1 < nblks) {
            CP_WAIT(0);
            __syncthreads();
        }
    }
}

// ------- fused SINGLE-PASS softmax + aggregate + bias(+elu): warp per dst ---
// 2-edge unrolled main loop for memory-level parallelism. (H=8, C=32 layers)
template <int H, int C, int OUTMODE>
__global__ void gat_agg_h(const __half* __restrict__ x,
                          const float* __restrict__ als,
                          const float* __restrict__ ald,
                          const int* __restrict__ rp,
                          const int* __restrict__ cs,
                          float* __restrict__ out,
                          __half* __restrict__ oh,
                          const float* __restrict__ bias,
                          int Nn, int do_elu) {
    constexpr int HC = H * C;
    int n = (blockIdx.x * blockDim.x + threadIdx.x) >> 5;
    int lane = threadIdx.x & 31;
    if (n >= Nn) return;

    int start = rp[n], end = rp[n + 1];
    float aldv = (lane < H) ? ald[n * H + lane] : 0.f;

    const int col0 = lane * 8;
    const bool act = col0 < HC;
    const int alane = act ? (col0 / C) : 0;
    float acc[8];
#pragma unroll
    for (int i = 0; i < 8; i++) acc[i] = 0.f;
    float sacc = 0.f;

    int k = start;
    for (; k + 1 < end; k += 2) {
        int s0 = cs[k], s1 = cs[k + 1];
        float e0 = 0.f, e1 = 0.f;
        if (lane < H) {
            float v0 = als[s0 * H + lane] + aldv;
            float v1 = als[s1 * H + lane] + aldv;
            v0 = v0 > 0.f ? v0 : 0.2f * v0;
            v1 = v1 > 0.f ? v1 : 0.2f * v1;
            e0 = __expf(v0);
            e1 = __expf(v1);
            sacc += e0 + e1;
        }
        float a0 = __shfl_sync(0xffffffffu, e0, alane);
        float a1 = __shfl_sync(0xffffffffu, e1, alane);
        if (act) {
            uint4 w0 = *(const uint4*)(x + (size_t)s0 * HC + col0);
            uint4 w1 = *(const uint4*)(x + (size_t)s1 * HC + col0);
            float2 f;
            f = __half22float2(*(__half2*)&w0.x); acc[0] += f.x * a0; acc[1] += f.y * a0;
            f = __half22float2(*(__half2*)&w0.y); acc[2] += f.x * a0; acc[3] += f.y * a0;
            f = __half22float2(*(__half2*)&w0.z); acc[4] += f.x * a0; acc[5] += f.y * a0;
            f = __half22float2(*(__half2*)&w0.w); acc[6] += f.x * a0; acc[7] += f.y * a0;
            f = __half22float2(*(__half2*)&w1.x); acc[0] += f.x * a1; acc[1] += f.y * a1;
            f = __half22float2(*(__half2*)&w1.y); acc[2] += f.x * a1; acc[3] += f.y * a1;
            f = __half22float2(*(__half2*)&w1.z); acc[4] += f.x * a1; acc[5] += f.y * a1;
            f = __half22float2(*(__half2*)&w1.w); acc[6] += f.x * a1; acc[7] += f.y * a1;
        }
    }
    if (k < end) {
        int s0 = cs[k];
        float e0 = 0.f;
        if (lane < H) {
            float v0 = als[s0 * H + lane] + aldv;
            v0 = v0 > 0.f ? v0 : 0.2f * v0;
            e0 = __expf(v0);
            sacc += e0;
        }
        float a0 = __shfl_sync(0xffffffffu, e0, alane);
        if (act) {
            uint4 w0 = *(const uint4*)(x + (size_t)s0 * HC + col0);
            float2 f;
            f = __half22float2(*(__half2*)&w0.x); acc[0] += f.x * a0; acc[1] += f.y * a0;
            f = __half22float2(*(__half2*)&w0.y); acc[2] += f.x * a0; acc[3] += f.y * a0;
            f = __half22float2(*(__half2*)&w0.z); acc[4] += f.x * a0; acc[5] += f.y * a0;
            f = __half22float2(*(__half2*)&w0.w); acc[6] += f.x * a0; acc[7] += f.y * a0;
        }
    }

    float inv_s = (lane < H && sacc > 0.f) ? __frcp_rn(sacc) : 0.f;
    float scale = __shfl_sync(0xffffffffu, inv_s, alane);

    if (act) {
        float o[8];
#pragma unroll
        for (int i = 0; i < 8; i++) {
            float v = acc[i] * scale + bias[col0 + i];
            if (do_elu) v = v > 0.f ? v : expm1f(v);
            o[i] = v;
        }
        if (OUTMODE == 0) {
            float* od = out + (size_t)n * HC + col0;
            *(float4*)(od)     = make_float4(o[0], o[1], o[2], o[3]);
            *(float4*)(od + 4) = make_float4(o[4], o[5], o[6], o[7]);
        } else {
            uint4 p;
            __half2 t0 = __floats2half2_rn(o[0], o[1]);
            __half2 t1 = __floats2half2_rn(o[2], o[3]);
            __half2 t2 = __floats2half2_rn(o[4], o[5]);
            __half2 t3 = __floats2half2_rn(o[6], o[7]);
            p.x = *(uint32_t*)&t0; p.y = *(uint32_t*)&t1;
            p.z = *(uint32_t*)&t2; p.w = *(uint32_t*)&t3;
            *(uint4*)(oh + (size_t)n * HC + col0) = p;
        }
    }
}

// ------- layer-2 aggregation: H=1, C=40, 4 nodes per warp (8-lane groups) ---
__global__ void gat_agg2_k(const __half* __restrict__ x,
                           const float* __restrict__ als,
                           const float* __restrict__ ald,
                           const int* __restrict__ rp,
                           const int* __restrict__ cs,
                           float* __restrict__ out,
                           const float* __restrict__ bias,
                           int Nn) {
    int warp = (blockIdx.x * blockDim.x + threadIdx.x) >> 5;
    int lane = threadIdx.x & 31;
    int g = lane >> 3, sl = lane & 7;
    int n = warp * 4 + g;
    bool nok = n < Nn;

    int start = nok ? rp[n] : 0;
    int end   = nok ? rp[n + 1] : 0;
    int cnt = end - start;
    int mc = cnt;
#pragma unroll
    for (int off = 8; off < 32; off <<= 1)
        mc = max(mc, __shfl_xor_sync(0xffffffffu, mc, off));

    float aldv = nok ? ald[n] : 0.f;
    const int col0 = sl * 8;
    const bool act = nok && col0 < 40;
    float acc[8];
#pragma unroll
    for (int i = 0; i < 8; i++) acc[i] = 0.f;
    float sacc = 0.f;

    for (int k = 0; k < mc; k++) {
        bool ok = k < cnt;
        int src = ok ? cs[start + k] : 0;
        float e = 0.f;
        if (sl == 0 && ok) {
            float v = als[src] + aldv;
            v = v > 0.f ? v : 0.2f * v;
            e = __expf(v);
            sacc += e;
        }
        float a = __shfl_sync(0xffffffffu, e, g * 8);
        if (act && ok) {
            uint4 w0 = *(const uint4*)(x + (size_t)src * 40 + col0);
            float2 f;
            f = __half22float2(*(__half2*)&w0.x); acc[0] += f.x * a; acc[1] += f.y * a;
            f = __half22float2(*(__half2*)&w0.y); acc[2] += f.x * a; acc[3] += f.y * a;
            f = __half22float2(*(__half2*)&w0.z); acc[4] += f.x * a; acc[5] += f.y * a;
            f = __half22float2(*(__half2*)&w0.w); acc[6] += f.x * a; acc[7] += f.y * a;
        }
    }

    float inv_s = (sl == 0 && sacc > 0.f) ? __frcp_rn(sacc) : 0.f;
    float scale = __shfl_sync(0xffffffffu, inv_s, g * 8);

    if (act) {
        float o[8];
#pragma unroll
        for (int i = 0; i < 8; i++)
            o[i] = acc[i] * scale + bias[col0 + i];
        float* od = out + (size_t)n * 40 + col0;
        *(float4*)(od)     = make_float4(o[0], o[1], o[2], o[3]);
        *(float4*)(od + 4) = make_float4(o[4], o[5], o[6], o[7]);
    }
}

// ---------------- launcher (single stream — graph-capture friendly) ---------
extern "C" void kernel_launch(void* const* d_in, const int* in_sizes, int n_in,
                              void* d_out, int out_size) {
    const float* feats = (const float*)d_in[0];
    const void*  ei    = d_in[1];
    const float* W0  = (const float*)d_in[2];
    const float* as0 = (const float*)d_in[3];
    const float* ad0 = (const float*)d_in[4];
    const float* b0  = (const float*)d_in[5];
    const float* W1  = (const float*)d_in[6];
    const float* as1 = (const float*)d_in[7];
    const float* ad1 = (const float*)d_in[8];
    const float* b1  = (const float*)d_in[9];
    const float* W2  = (const float*)d_in[10];
    const float* as2 = (const float*)d_in[11];
    const float* ad2 = (const float*)d_in[12];
    const float* b2  = (const float*)d_in[13];

    int N  = in_sizes[0] / FIN;
    int NE = in_sizes[1] / 2;
    int ET = NE + N;
    float* out = (float*)d_out;
    (void)n_in; (void)out_size;

    __half *pxh, *pa16, *pwt;
    float *pals, *pald;
    int *pdeg, *prp, *pcur, *pcs, *pbs;
    cudaGetSymbolAddress((void**)&pxh,  g_xh);
    cudaGetSymbolAddress((void**)&pa16, g_a16);
    cudaGetSymbolAddress((void**)&pals, g_als);
    cudaGetSymbolAddress((void**)&pald, g_ald);
    cudaGetSymbolAddress((void**)&pdeg, g_deg);
    cudaGetSymbolAddress((void**)&prp,  g_rp);
    cudaGetSymbolAddress((void**)&pcur, g_cur);
    cudaGetSymbolAddress((void**)&pcs,  g_csrc);
    cudaGetSymbolAddress((void**)&pbs,  g_bs);
    cudaGetSymbolAddress((void**)&pwt,  g_wt);

    // SMEM: (K+8)*2*(256 + 2*64) bytes; K=256 -> 202752, K=128 -> 104448
    const int SM_K256 = (256 + 8) * 2 * (BM + 2 * BN);
    cudaFuncSetAttribute(gemm_as, cudaFuncAttributeMaxDynamicSharedMemorySize, SM_K256);
    const int SM_K128 = (128 + 8) * 2 * (BM + 2 * BN);

    int ethreads = (ET + 255) / 256;
    int nwarps_b = (N * 32 + 255) / 256;
    int nwarps_q = ((N + 3) / 4 * 32 + 255) / 256;
    dim3 gridg(1, (N + BM - 1) / BM);

    // (1) dtype detect + zero(deg)
    detect_zero_k<<<256, 256>>>((const unsigned int*)ei, pdeg, N + 1);
    // (2) all weights (one kernel)
    wt_all_k<<<(32768 + 65536 + 40 * 256 + 255) / 256, 256>>>(W0, W1, W2, pwt);
    // (3) layer-0 A convert
    asplit_k<<<(N * 128 / 4 + 255) / 256, 256>>>(feats, pa16, N * 128 / 4);
    // (4) layer-0 GEMM  <-- profiled launch
    gemm_as<<<gridg, 256, SM_K128>>>(pa16, pwt, pxh, pals, pald,
                                     as0, ad0, N, 128, 256, 1);

    // --- CSR build (inline edge decode; must complete before agg0) ---
    count_k<<<ethreads, 256>>>(ei, NE, N);
    int nb1 = (N + 1023) / 1024;
    scan1_k<<<nb1, 1024>>>(pdeg, prp, pbs, N);
    scan2_k<<<1, 256>>>(pbs, nb1);
    scan3_k<<<(N + 255) / 256, 256>>>(prp, pbs, pcur, N, ET);
    fill_k<<<ethreads, 256>>>(ei, NE, N);

    // --- layer 0 aggregation (writes fp16 A for layer 1) ---
    gat_agg_h<8, 32, 1><<<nwarps_b, 256>>>(pxh, pals, pald, prp, pcs,
                                           nullptr, pa16, b0, N, 1);

    // --- layer 1: 256 -> 8x32 ---
    gemm_as<<<gridg, 256, SM_K256>>>(pa16, pwt + 65536, pxh,
                                     pals, pald, as1, ad1, N, 256, 256, 1);
    gat_agg_h<8, 32, 1><<<nwarps_b, 256>>>(pxh, pals, pald, prp, pcs,
                                           nullptr, pa16, b1, N, 1);

    // --- layer 2: 256 -> 1x40 (al fused into GEMM epilogue, mode 2) ---
    gemm_as<<<gridg, 256, SM_K256>>>(pa16, pwt + 131072,
                                     pxh, pals, pald, as2, ad2, N, 256, 40, 2);
    gat_agg2_k<<<nwarps_q, 256>>>(pxh, pals, pald, prp, pcs, out, b2, N);
}